// round 5
// baseline (speedup 1.0000x reference)
#include <cuda_runtime.h>
#include <math.h>
#include <stdint.h>

#define BB 2
#define NS 4
#define TT 2048
#define DD 1024
#define EE 16
#define NDIM 4096
#define DFFN 1656
#define LDP 1664
#define BT (BB*TT)
#define CAP BT
#define EPS_F 1.1920929e-7f
#define STGF 13824              // floats per stage: (128+256)*36
#define SMEM_DYN (3*STGF*4)     // 165888 B

// ---- device scratch ----
__device__ __align__(16) float g_base[(size_t)BT*NDIM];
__device__ __align__(16) float g_HN [(size_t)EE*CAP*DD];
__device__ __align__(16) float g_T1 [(size_t)EE*CAP*DD];
__device__ __align__(16) float g_GS [(size_t)EE*CAP*DD];
__device__ __align__(16) float g_P1 [(size_t)EE*CAP*LDP];
__device__ __align__(16) float g_P2 [(size_t)EE*CAP*LDP];
__device__ __align__(16) float g_OUT[(size_t)EE*CAP*DD];
__device__ __align__(16) float g_dots[(size_t)BT*384];
__device__ __align__(16) float g_phiW[(size_t)EE*24*NDIM];
__device__ __align__(16) float g_wd[(size_t)EE*DD*DD];
__device__ __align__(16) float g_wu[(size_t)EE*DD*DD];
__device__ __align__(16) float g_gt[(size_t)EE*DFFN*DD];
__device__ __align__(16) float g_up[(size_t)EE*DFFN*DD];
__device__ __align__(16) float g_dn[(size_t)EE*DD*LDP];
__device__ float g_srms[BT];
__device__ int   g_row[BT*EE];
__device__ float g_gatev[BT*EE];
__device__ int   g_tok[EE*CAP];
__device__ int   g_cnt[EE];
__device__ float g_Hpost[(size_t)EE*CAP*NS];
__device__ float g_Hres[(size_t)EE*CAP*16];

// ---- helpers ----
__device__ __forceinline__ float f2tf_f(float f) {
    uint32_t u;
    asm("cvt.rna.tf32.f32 %0, %1;" : "=r"(u) : "f"(f));
    return __uint_as_float(u);
}
__device__ __forceinline__ int posk(int k) { return ((k & 3) << 1) | ((k >> 2) & 1); }
__device__ __forceinline__ int invk(int p) { return ((p & 1) << 2) | (p >> 1); }
__device__ __forceinline__ void mma8(float* c, const uint32_t* a, uint32_t b0, uint32_t b1) {
    asm volatile(
        "mma.sync.aligned.m16n8k8.row.col.f32.tf32.tf32.f32 "
        "{%0,%1,%2,%3}, {%4,%5,%6,%7}, {%8,%9}, {%0,%1,%2,%3};"
        : "+f"(c[0]), "+f"(c[1]), "+f"(c[2]), "+f"(c[3])
        : "r"(a[0]), "r"(a[1]), "r"(a[2]), "r"(a[3]), "r"(b0), "r"(b1));
}
__device__ __forceinline__ void cp16(uint32_t s, const void* g, bool pr) {
    int b = pr ? 16 : 0;
    asm volatile("cp.async.cg.shared.global [%0], [%1], 16, %2;" :: "r"(s), "l"(g), "r"(b));
}

__global__ void k_zero() { if (threadIdx.x < EE) g_cnt[threadIdx.x] = 0; }

// ---- router gate + token rms ----
__global__ void __launch_bounds__(256) k_gate(const float* __restrict__ stream,
                                              const float* __restrict__ router_w,
                                              float* __restrict__ out_gate)
{
    int token = blockIdx.x, b = token / TT, t = token % TT, tid = threadIdx.x;
    __shared__ float route[DD], red[256], logit[EE];
    const float* sp0 = stream + ((size_t)b * NS * TT + t) * DD;
    float ss = 0.f;
    for (int dd = tid; dd < DD; dd += 256) {
        float v0 = sp0[dd], v1 = sp0[(size_t)TT*DD + dd];
        float v2 = sp0[2*(size_t)TT*DD + dd], v3 = sp0[3*(size_t)TT*DD + dd];
        ss += v0*v0 + v1*v1 + v2*v2 + v3*v3;
        route[dd] = 0.25f * (v0 + v1 + v2 + v3);
    }
    red[tid] = ss; __syncthreads();
    for (int s = 128; s > 0; s >>= 1) { if (tid < s) red[tid] += red[tid+s]; __syncthreads(); }
    if (tid == 0) g_srms[token] = rsqrtf(red[0] / (float)NDIM + EPS_F);
    int warp = tid >> 5, lane = tid & 31;
    for (int e = warp; e < EE; e += 8) {
        const float* rw = router_w + (size_t)e * DD;
        float acc = 0.f;
        for (int dd = lane; dd < DD; dd += 32) acc += route[dd] * rw[dd];
        #pragma unroll
        for (int o = 16; o > 0; o >>= 1) acc += __shfl_down_sync(0xffffffffu, acc, o);
        if (lane == 0) logit[e] = acc;
    }
    __syncthreads();
    if (tid == 0) {
        float p[EE], mx = -1e30f;
        #pragma unroll
        for (int e = 0; e < EE; e++) mx = fmaxf(mx, logit[e]);
        float sum = 0.f;
        #pragma unroll
        for (int e = 0; e < EE; e++) { p[e] = expf(logit[e] - mx); sum += p[e]; }
        float inv = 1.f / sum;
        #pragma unroll
        for (int e = 0; e < EE; e++) p[e] *= inv;
        int ord[EE];
        #pragma unroll
        for (int e = 0; e < EE; e++) ord[e] = e;
        for (int i = 1; i < EE; i++) {
            int oi = ord[i]; float pi = p[oi]; int j = i - 1;
            while (j >= 0 && p[ord[j]] < pi) { ord[j+1] = ord[j]; j--; }
            ord[j+1] = oi;
        }
        float cum = 0.f, gate[EE];
        #pragma unroll
        for (int e = 0; e < EE; e++) gate[e] = 0.f;
        for (int r = 0; r < EE; r++) {
            int e = ord[r];
            if ((r == 0) || (cum < 0.8f && r < 4)) gate[e] = p[e];
            cum += p[e];
        }
        for (int e = 0; e < EE; e++) {
            float g = gate[e];
            out_gate[(size_t)token*EE + e] = g;
            g_gatev[token*EE + e] = g;
            int row = -1;
            if (g > 0.f) { row = atomicAdd(&g_cnt[e], 1); g_tok[e*CAP + row] = token; }
            g_row[token*EE + e] = row;
        }
    }
}

// ---- base = rms(flat stream), tf32-rounded, k-interleaved ----
__global__ void __launch_bounds__(256) k_base(const float* __restrict__ stream)
{
    int token = blockIdx.x, b = token / TT, t = token % TT;
    float s = g_srms[token];
    const float* sp0 = stream + ((size_t)b * NS * TT + t) * DD;
    float* dst = g_base + (size_t)token * NDIM;
    for (int j = threadIdx.x; j < NDIM; j += 256) {
        int jj = (j & ~7) | invk(j & 7);     // source element for dst slot j
        int i = jj >> 10, dd = jj & 1023;
        dst[j] = f2tf_f(sp0[(size_t)i*TT*DD + dd] * s);
    }
}

// ---- pack phi weights (fold mhc norm), rounded + interleaved ----
__global__ void __launch_bounds__(256) k_pack(const float* __restrict__ mhc_norm_w,
                                              const float* __restrict__ pw,
                                              const float* __restrict__ ow,
                                              const float* __restrict__ rw)
{
    int base = blockIdx.x * 1024;
    #pragma unroll
    for (int u = 0; u < 4; u++) {
        int idx = base + u*256 + threadIdx.x;
        int e = idx / (24*NDIM), rem = idx - e*24*NDIM, r = rem >> 12, jd = rem & 4095;
        int j = (jd & ~7) | invk(jd & 7);
        float w;
        if (r < 4)      w = pw[((size_t)e*4 + r)*NDIM + j];
        else if (r < 8) w = ow[((size_t)e*4 + (r-4))*NDIM + j];
        else            w = rw[((size_t)e*16 + (r-8))*NDIM + j];
        g_phiW[idx] = f2tf_f(w * mhc_norm_w[(size_t)e*NDIM + j]);
    }
}

// ---- generic weight pack: rounded + interleaved + K-pad ----
__global__ void __launch_bounds__(256) k_packw(const float* __restrict__ src,
                                               float* __restrict__ dst,
                                               int Kact, int Kpad, long total)
{
    long i0 = (long)blockIdx.x * 1024 + threadIdx.x;
    #pragma unroll
    for (int u = 0; u < 4; u++) {
        long idx = i0 + u*256;
        if (idx >= total) return;
        long r = idx / Kpad;
        int kd = (int)(idx - r * Kpad);
        int k = (kd & ~7) | invk(kd & 7);
        dst[idx] = (k < Kact) ? f2tf_f(src[r * Kact + k]) : 0.f;
    }
}

// ---- tf32 GEMM: C[m,n] = epi( sum_k A[m,k]*W[n,k] ), operands pre-rounded+interleaved
// MODE 0 raw->Cf, 1 silu->Ci(int), 2 sigm->Cf, 3 silu->Cf, 4 mulAux->Ci(int,+pad0), 5 mulAux->Cf
template <int MODE>
__global__ void __launch_bounds__(256, 1) k_gemm(
    const float* __restrict__ A, int lda,
    const float* __restrict__ W, int ldw, int Ntot, int KT,
    float* __restrict__ Cf, float* __restrict__ Ci, int ldc,
    const float* __restrict__ Aux, int ldaux, int cntOv)
{
    extern __shared__ float sm[];
    int e = blockIdx.z;
    int cnt = (cntOv >= 0) ? cntOv : g_cnt[e];
    int m0 = blockIdx.x * 128;
    if (m0 >= cnt) return;
    int n0 = blockIdx.y * 256;

    A += (size_t)e * CAP * lda;
    W += (size_t)e * Ntot * ldw;
    size_t co = (size_t)e * CAP * ldc;
    if (Cf) Cf += co;
    if (Ci) Ci += co;
    if (Aux) Aux += (size_t)e * CAP * ldaux;

    uint32_t sb = (uint32_t)__cvta_generic_to_shared(sm);
    int tid = threadIdx.x, warp = tid >> 5, lane = tid & 31;
    int wm = warp >> 2, wn = warp & 3;          // 2 x 4 warps, each 64m x 64n
    int qr = lane >> 2, qc = lane & 3;

    float acc[4][8][4];
    #pragma unroll
    for (int mt = 0; mt < 4; mt++)
        #pragma unroll
        for (int nt = 0; nt < 8; nt++)
            #pragma unroll
            for (int q = 0; q < 4; q++) acc[mt][nt][q] = 0.f;

    auto load = [&](int kt, int s) {
        int k0 = kt * 32;
        uint32_t sA = sb + s * (STGF * 4);
        #pragma unroll
        for (int i = 0; i < 4; i++) {
            int f = tid + i*256, r = f >> 3, c = f & 7;
            cp16(sA + r*144 + c*16, A + (size_t)(m0 + r)*lda + k0 + c*4, true);
        }
        uint32_t sB = sA + 18432;
        #pragma unroll
        for (int i = 0; i < 8; i++) {
            int f = tid + i*256, r = f >> 3, c = f & 7;
            bool pr = (n0 + r) < Ntot;
            cp16(sB + r*144 + c*16, W + (size_t)(n0 + r)*ldw + k0 + c*4, pr);
        }
        asm volatile("cp.async.commit_group;");
    };

    load(0, 0);
    if (KT > 1) load(1, 1); else asm volatile("cp.async.commit_group;");

    for (int kt = 0; kt < KT; kt++) {
        asm volatile("cp.async.wait_group 1;" ::: "memory");
        __syncthreads();
        if (kt + 2 < KT) load(kt + 2, (kt + 2) % 3);
        else asm volatile("cp.async.commit_group;");

        const float* Asm = sm + (kt % 3) * STGF;
        const float* Bsm = Asm + 4608;
        #pragma unroll
        for (int ks = 0; ks < 4; ks++) {
            float2 a[4][2];
            #pragma unroll
            for (int mt = 0; mt < 4; mt++) {
                const float* ap = Asm + (wm*64 + mt*16 + qr)*36 + ks*8 + qc*2;
                a[mt][0] = *(const float2*)ap;
                a[mt][1] = *(const float2*)(ap + 288);
            }
            #pragma unroll
            for (int nt = 0; nt < 8; nt++) {
                float2 bb = *(const float2*)(Bsm + (wn*64 + nt*8 + qr)*36 + ks*8 + qc*2);
                uint32_t b0 = __float_as_uint(bb.x), b1 = __float_as_uint(bb.y);
                #pragma unroll
                for (int mt = 0; mt < 4; mt++) {
                    uint32_t av[4] = {__float_as_uint(a[mt][0].x), __float_as_uint(a[mt][1].x),
                                      __float_as_uint(a[mt][0].y), __float_as_uint(a[mt][1].y)};
                    mma8(acc[mt][nt], av, b0, b1);
                }
            }
        }
        __syncthreads();
    }

    // epilogue
    #pragma unroll
    for (int mt = 0; mt < 4; mt++) {
        #pragma unroll
        for (int nt = 0; nt < 8; nt++) {
            int n = n0 + wn*64 + nt*8 + qc*2;
            #pragma unroll
            for (int half = 0; half < 2; half++) {
                int m = m0 + wm*64 + mt*16 + qr + half*8;
                if (m >= cnt) continue;
                float v0 = acc[mt][nt][half*2], v1 = acc[mt][nt][half*2 + 1];
                size_t off = (size_t)m * ldc + n;
                if (MODE == 0) {
                    if (n < Ntot) { float2 s2; s2.x = v0; s2.y = v1; *(float2*)(Cf + off) = s2; }
                } else if (MODE == 2) {
                    if (n < Ntot) {
                        float2 s2; s2.x = 1.f/(1.f+expf(-v0)); s2.y = 1.f/(1.f+expf(-v1));
                        *(float2*)(Cf + off) = s2;
                    }
                } else if (MODE == 3) {
                    if (n < Ntot) {
                        float2 s2; s2.x = v0/(1.f+expf(-v0)); s2.y = v1/(1.f+expf(-v1));
                        *(float2*)(Cf + off) = s2;
                    }
                } else if (MODE == 5) {
                    if (n < Ntot) {
                        float2 s2; s2.x = v0 * Aux[(size_t)m*ldaux + n];
                        s2.y = v1 * Aux[(size_t)m*ldaux + n + 1];
                        *(float2*)(Cf + off) = s2;
                    }
                } else {  // 1, 4: interleaved tf32 outputs
                    size_t rowo = (size_t)m * ldc + (n & ~7);
                    int p0 = posk(n & 7), p1 = posk((n + 1) & 7);
                    if (n < Ntot) {
                        float x0, x1;
                        if (MODE == 1) { x0 = v0/(1.f+expf(-v0)); x1 = v1/(1.f+expf(-v1)); }
                        else { x0 = v0 * Aux[(size_t)m*ldaux + n]; x1 = v1 * Aux[(size_t)m*ldaux + n + 1]; }
                        Ci[rowo + p0] = f2tf_f(x0);
                        Ci[rowo + p1] = f2tf_f(x1);
                    } else if (MODE == 4 && n < ldc) {
                        Ci[rowo + p0] = 0.f;
                        Ci[rowo + p1] = 0.f;
                    }
                }
            }
        }
    }
}

// ---- per active pair: gates, sinkhorn, h, hn (rounded + interleaved) ----
__global__ void __launch_bounds__(128) k_hn(const float* __restrict__ stream,
                                            const float* __restrict__ b_pre,
                                            const float* __restrict__ b_post,
                                            const float* __restrict__ b_res,
                                            const float* __restrict__ alpha_pre,
                                            const float* __restrict__ alpha_post,
                                            const float* __restrict__ alpha_res,
                                            const float* __restrict__ sw_norm_w)
{
    int row = blockIdx.x, e = blockIdx.y;
    if (row >= g_cnt[e]) return;
    int token = g_tok[e*CAP + row], b = token / TT, t = token % TT, tid = threadIdx.x;
    __shared__ float hpre[NS], red2[4];

    if (tid == 0) {
        const float* d = g_dots + (size_t)token*384 + e*24;
        size_t slot = (size_t)e*CAP + row;
        float ap = alpha_pre[e], ao = alpha_post[e], ar = alpha_res[e];
        #pragma unroll
        for (int i = 0; i < NS; i++)
            hpre[i] = 1.f / (1.f + expf(-(ap*d[i] + b_pre[e*NS+i])));
        #pragma unroll
        for (int i = 0; i < NS; i++)
            g_Hpost[slot*NS+i] = 2.f / (1.f + expf(-(ao*d[4+i] + b_post[e*NS+i])));
        float M[16];
        #pragma unroll
        for (int k = 0; k < 16; k++) M[k] = expf(ar*d[8+k] + b_res[e*16+k]);
        for (int it = 0; it < 6; it++) {
            #pragma unroll
            for (int i = 0; i < 4; i++) {
                float ir = 1.f / (M[i*4]+M[i*4+1]+M[i*4+2]+M[i*4+3]);
                M[i*4]*=ir; M[i*4+1]*=ir; M[i*4+2]*=ir; M[i*4+3]*=ir;
            }
            #pragma unroll
            for (int j = 0; j < 4; j++) {
                float ic = 1.f / (M[j]+M[4+j]+M[8+j]+M[12+j]);
                M[j]*=ic; M[4+j]*=ic; M[8+j]*=ic; M[12+j]*=ic;
            }
        }
        #pragma unroll
        for (int k = 0; k < 16; k++) g_Hres[slot*16+k] = M[k];
    }
    __syncthreads();

    const float* sp0 = stream + ((size_t)b*NS*TT + t) * DD;
    float h0 = hpre[0], h1 = hpre[1], h2 = hpre[2], h3 = hpre[3];
    float hreg[8], hq = 0.f;
    #pragma unroll
    for (int u = 0; u < 8; u++) {
        int dd = tid + u*128;
        float h = h0*sp0[dd] + h1*sp0[(size_t)TT*DD+dd]
                + h2*sp0[2*(size_t)TT*DD+dd] + h3*sp0[3*(size_t)TT*DD+dd];
        hreg[u] = h; hq += h*h;
    }
    int lane = tid & 31, warp = tid >> 5;
    #pragma unroll
    for (int o = 16; o > 0; o >>= 1) hq += __shfl_down_sync(0xffffffffu, hq, o);
    if (lane == 0) red2[warp] = hq;
    __syncthreads();
    if (tid == 0) red2[0] = rsqrtf((red2[0]+red2[1]+red2[2]+red2[3]) / (float)DD + EPS_F);
    __syncthreads();
    float sh = red2[0];
    const float* snw = sw_norm_w + (size_t)e*DD;
    float* hn = g_HN + ((size_t)e*CAP + row) * DD;
    #pragma unroll
    for (int u = 0; u < 8; u++) {
        int dd = tid + u*128;
        float v = hreg[u] * sh * snw[dd];
        hn[(dd & ~7) | posk(dd & 7)] = f2tf_f(v);
    }
}

// ---- combine res + post ----
__global__ void __launch_bounds__(128) k_out(const float* __restrict__ stream,
                                             float* __restrict__ outp)
{
    int token = blockIdx.x, b = token / TT, t = token % TT, tid = threadIdx.x;
    const float* sp0 = stream + ((size_t)b*NS*TT + t) * DD;
    float st[4][8], acc[4][8];
    #pragma unroll
    for (int i = 0; i < 4; i++)
        #pragma unroll
        for (int j = 0; j < 8; j++) {
            st[i][j] = sp0[(size_t)i*TT*DD + tid + j*128];
            acc[i][j] = 0.f;
        }
    for (int e = 0; e < EE; e++) {
        int row = g_row[token*EE + e];
        if (row < 0) continue;
        float g = g_gatev[token*EE + e];
        size_t slot = (size_t)e*CAP + row;
        float Hr[16], Hp[4];
        #pragma unroll
        for (int k = 0; k < 16; k++) Hr[k] = g_Hres[slot*16+k];
        #pragma unroll
        for (int i = 0; i < 4; i++) Hp[i] = g_Hpost[slot*4+i];
        const float* o = g_OUT + slot*DD;
        #pragma unroll
        for (int j = 0; j < 8; j++) {
            float ov = o[tid + j*128];
            #pragma unroll
            for (int i = 0; i < 4; i++) {
                float r = Hr[i*4]*st[0][j] + Hr[i*4+1]*st[1][j]
                        + Hr[i*4+2]*st[2][j] + Hr[i*4+3]*st[3][j];
                acc[i][j] += g * (r + Hp[i]*ov);
            }
        }
    }
    #pragma unroll
    for (int i = 0; i < 4; i++)
        #pragma unroll
        for (int j = 0; j < 8; j++)
            outp[((size_t)(b*NS+i)*TT + t)*DD + tid + j*128] = acc[i][j];
}

#define GSA(p, s) cudaGetSymbolAddress((void**)&p, s)

extern "C" void kernel_launch(void* const* d_in, const int* in_sizes, int n_in,
                              void* d_out, int out_size)
{
    (void)in_sizes; (void)n_in; (void)out_size;
    const float* stream   = (const float*)d_in[0];
    const float* router_w = (const float*)d_in[1];
    const float* mhc      = (const float*)d_in[2];
    const float* phi_pre  = (const float*)d_in[3];
    const float* phi_post = (const float*)d_in[4];
    const float* phi_res  = (const float*)d_in[5];
    const float* b_pre    = (const float*)d_in[6];
    const float* b_post   = (const float*)d_in[7];
    const float* b_res    = (const float*)d_in[8];
    const float* a_pre    = (const float*)d_in[9];
    const float* a_post   = (const float*)d_in[10];
    const float* a_res    = (const float*)d_in[11];
    const float* sw_nw    = (const float*)d_in[12];
    const float* wd_w     = (const float*)d_in[13];
    const float* wu_w     = (const float*)d_in[14];
    const float* gate_w   = (const float*)d_in[15];
    const float* up_w     = (const float*)d_in[16];
    const float* down_w   = (const float*)d_in[17];

    float* outp = (float*)d_out;
    float* out_gate = outp + (size_t)BB*NS*TT*DD;

    cudaFuncSetAttribute(k_gemm<0>, cudaFuncAttributeMaxDynamicSharedMemorySize, SMEM_DYN);
    cudaFuncSetAttribute(k_gemm<1>, cudaFuncAttributeMaxDynamicSharedMemorySize, SMEM_DYN);
    cudaFuncSetAttribute(k_gemm<2>, cudaFuncAttributeMaxDynamicSharedMemorySize, SMEM_DYN);
    cudaFuncSetAttribute(k_gemm<3>, cudaFuncAttributeMaxDynamicSharedMemorySize, SMEM_DYN);
    cudaFuncSetAttribute(k_gemm<4>, cudaFuncAttributeMaxDynamicSharedMemorySize, SMEM_DYN);
    cudaFuncSetAttribute(k_gemm<5>, cudaFuncAttributeMaxDynamicSharedMemorySize, SMEM_DYN);

    float *base, *HN, *T1, *GS, *P1, *P2, *OUT, *dots, *phiW, *wd, *wu, *gt, *up, *dn;
    GSA(base, g_base); GSA(HN, g_HN); GSA(T1, g_T1); GSA(GS, g_GS);
    GSA(P1, g_P1); GSA(P2, g_P2); GSA(OUT, g_OUT); GSA(dots, g_dots);
    GSA(phiW, g_phiW); GSA(wd, g_wd); GSA(wu, g_wu); GSA(gt, g_gt);
    GSA(up, g_up); GSA(dn, g_dn);

    k_zero<<<1, 32>>>();
    k_gate<<<BT, 256>>>(stream, router_w, out_gate);
    k_base<<<BT, 256>>>(stream);
    k_pack<<<(EE*24*NDIM)/1024, 256>>>(mhc, phi_pre, phi_post, phi_res);
    {
        long t1 = (long)EE*DD*DD, t2 = (long)EE*DFFN*DD, t3 = (long)EE*DD*LDP;
        k_packw<<<(unsigned)((t1+1023)/1024), 256>>>(wd_w,   wd, DD, DD, t1);
        k_packw<<<(unsigned)((t1+1023)/1024), 256>>>(wu_w,   wu, DD, DD, t1);
        k_packw<<<(unsigned)((t2+1023)/1024), 256>>>(gate_w, gt, DD, DD, t2);
        k_packw<<<(unsigned)((t2+1023)/1024), 256>>>(up_w,   up, DD, DD, t2);
        k_packw<<<(unsigned)((t3+1023)/1024), 256>>>(down_w, dn, DFFN, LDP, t3);
    }

    // dots = base @ phiW^T  (N=384, K=4096), plain f32 out
    k_gemm<0><<<dim3(32,2,1), 256, SMEM_DYN>>>(base, NDIM, phiW, NDIM, 384, NDIM/32,
                                               dots, (float*)0, 384, (const float*)0, 0, BT);

    k_hn<<<dim3(CAP, EE), 128>>>(stream, b_pre, b_post, b_res, a_pre, a_post, a_res, sw_nw);

    // T1 = silu(HN @ wd^T) -> interleaved tf32
    k_gemm<1><<<dim3(32,4,EE), 256, SMEM_DYN>>>(HN, DD, wd, DD, DD, DD/32,
                                                (float*)0, T1, DD, (const float*)0, 0, -1);
    // GS = sigmoid(T1 @ wu^T) -> f32
    k_gemm<2><<<dim3(32,4,EE), 256, SMEM_DYN>>>(T1, DD, wu, DD, DD, DD/32,
                                                GS, (float*)0, DD, (const float*)0, 0, -1);
    // P1 = silu(HN @ gate^T) -> f32 (ld LDP)
    k_gemm<3><<<dim3(32,7,EE), 256, SMEM_DYN>>>(HN, DD, gt, DD, DFFN, DD/32,
                                                P1, (float*)0, LDP, (const float*)0, 0, -1);
    // P2 = (HN @ up^T) * P1 -> interleaved tf32, zero-padded to LDP
    k_gemm<4><<<dim3(32,7,EE), 256, SMEM_DYN>>>(HN, DD, up, DD, DFFN, DD/32,
                                                (float*)0, P2, LDP, P1, LDP, -1);
    // OUT = (P2 @ dn^T) * GS -> f32
    k_gemm<5><<<dim3(32,4,EE), 256, SMEM_DYN>>>(P2, LDP, dn, LDP, DD, LDP/32,
                                                OUT, (float*)0, DD, GS, DD, -1);

    k_out<<<BT, 128>>>(stream, outp);
}

// round 6
// speedup vs baseline: 1.1560x; 1.1560x over previous
#include <cuda_runtime.h>
#include <math.h>
#include <stdint.h>

#define BB 2
#define NS 4
#define TT 2048
#define DD 1024
#define EE 16
#define NDIM 4096
#define DFFN 1656
#define LDP 1664
#define BT (BB*TT)
#define CAP BT
#define EPS_F 1.1920929e-7f
#define SMEM_DYN 73728

// ---- device scratch ----
__device__ __align__(16) float g_base[(size_t)BT*NDIM];
__device__ __align__(16) float g_HN [(size_t)EE*CAP*DD];
__device__ __align__(16) float g_T1 [(size_t)EE*CAP*DD];
__device__ __align__(16) float g_GS [(size_t)EE*CAP*DD];
__device__ __align__(16) float g_P1 [(size_t)EE*CAP*LDP];
__device__ __align__(16) float g_P2 [(size_t)EE*CAP*LDP];
__device__ __align__(16) float g_OUT[(size_t)EE*CAP*DD];
__device__ __align__(16) float g_dots[(size_t)BT*384];
__device__ __align__(16) float g_phiW[(size_t)EE*24*NDIM];
__device__ __align__(16) float g_wd[(size_t)EE*DD*DD];
__device__ __align__(16) float g_wu[(size_t)EE*DD*DD];
__device__ __align__(16) float g_gt[(size_t)EE*DFFN*DD];
__device__ __align__(16) float g_up[(size_t)EE*DFFN*DD];
__device__ __align__(16) float g_dn[(size_t)EE*DD*LDP];
__device__ float g_srms[BT];
__device__ int   g_row[BT*EE];
__device__ float g_gatev[BT*EE];
__device__ int   g_tok[EE*CAP];
__device__ int   g_cnt[EE];
__device__ float g_Hpost[(size_t)EE*CAP*NS];
__device__ float g_Hres[(size_t)EE*CAP*16];

// ---- helpers ----
__device__ __forceinline__ float f2tf_f(float f) {
    uint32_t u;
    asm("cvt.rna.tf32.f32 %0, %1;" : "=r"(u) : "f"(f));
    return __uint_as_float(u);
}
__device__ __forceinline__ int posk(int k) { return ((k & 3) << 1) | ((k >> 2) & 1); }
__device__ __forceinline__ int invk(int p) { return ((p & 1) << 2) | (p >> 1); }
__device__ __forceinline__ void mma8(float* c, uint32_t a0, uint32_t a1, uint32_t a2,
                                     uint32_t a3, uint32_t b0, uint32_t b1) {
    asm volatile(
        "mma.sync.aligned.m16n8k8.row.col.f32.tf32.tf32.f32 "
        "{%0,%1,%2,%3}, {%4,%5,%6,%7}, {%8,%9}, {%0,%1,%2,%3};"
        : "+f"(c[0]), "+f"(c[1]), "+f"(c[2]), "+f"(c[3])
        : "r"(a0), "r"(a1), "r"(a2), "r"(a3), "r"(b0), "r"(b1));
}
__device__ __forceinline__ void cp16(uint32_t s, const void* g, bool pr) {
    int b = pr ? 16 : 0;
    asm volatile("cp.async.cg.shared.global [%0], [%1], 16, %2;" :: "r"(s), "l"(g), "r"(b));
}

__global__ void k_zero() { if (threadIdx.x < EE) g_cnt[threadIdx.x] = 0; }

// ---- router gate + token rms ----
__global__ void __launch_bounds__(256) k_gate(const float* __restrict__ stream,
                                              const float* __restrict__ router_w,
                                              float* __restrict__ out_gate)
{
    int token = blockIdx.x, b = token / TT, t = token % TT, tid = threadIdx.x;
    __shared__ float route[DD], red[256], logit[EE];
    const float* sp0 = stream + ((size_t)b * NS * TT + t) * DD;
    float ss = 0.f;
    for (int dd = tid; dd < DD; dd += 256) {
        float v0 = sp0[dd], v1 = sp0[(size_t)TT*DD + dd];
        float v2 = sp0[2*(size_t)TT*DD + dd], v3 = sp0[3*(size_t)TT*DD + dd];
        ss += v0*v0 + v1*v1 + v2*v2 + v3*v3;
        route[dd] = 0.25f * (v0 + v1 + v2 + v3);
    }
    red[tid] = ss; __syncthreads();
    for (int s = 128; s > 0; s >>= 1) { if (tid < s) red[tid] += red[tid+s]; __syncthreads(); }
    if (tid == 0) g_srms[token] = rsqrtf(red[0] / (float)NDIM + EPS_F);
    int warp = tid >> 5, lane = tid & 31;
    for (int e = warp; e < EE; e += 8) {
        const float* rw = router_w + (size_t)e * DD;
        float acc = 0.f;
        for (int dd = lane; dd < DD; dd += 32) acc += route[dd] * rw[dd];
        #pragma unroll
        for (int o = 16; o > 0; o >>= 1) acc += __shfl_down_sync(0xffffffffu, acc, o);
        if (lane == 0) logit[e] = acc;
    }
    __syncthreads();
    if (tid == 0) {
        float p[EE], mx = -1e30f;
        #pragma unroll
        for (int e = 0; e < EE; e++) mx = fmaxf(mx, logit[e]);
        float sum = 0.f;
        #pragma unroll
        for (int e = 0; e < EE; e++) { p[e] = expf(logit[e] - mx); sum += p[e]; }
        float inv = 1.f / sum;
        #pragma unroll
        for (int e = 0; e < EE; e++) p[e] *= inv;
        int ord[EE];
        #pragma unroll
        for (int e = 0; e < EE; e++) ord[e] = e;
        for (int i = 1; i < EE; i++) {
            int oi = ord[i]; float pi = p[oi]; int j = i - 1;
            while (j >= 0 && p[ord[j]] < pi) { ord[j+1] = ord[j]; j--; }
            ord[j+1] = oi;
        }
        float cum = 0.f, gate[EE];
        #pragma unroll
        for (int e = 0; e < EE; e++) gate[e] = 0.f;
        for (int r = 0; r < EE; r++) {
            int e = ord[r];
            if ((r == 0) || (cum < 0.8f && r < 4)) gate[e] = p[e];
            cum += p[e];
        }
        for (int e = 0; e < EE; e++) {
            float g = gate[e];
            out_gate[(size_t)token*EE + e] = g;
            g_gatev[token*EE + e] = g;
            int row = -1;
            if (g > 0.f) { row = atomicAdd(&g_cnt[e], 1); g_tok[e*CAP + row] = token; }
            g_row[token*EE + e] = row;
        }
    }
}

// ---- base: tf32-rounded + k-interleaved ----
__global__ void __launch_bounds__(256) k_base(const float* __restrict__ stream)
{
    int token = blockIdx.x, b = token / TT, t = token % TT;
    float s = g_srms[token];
    const float* sp0 = stream + ((size_t)b * NS * TT + t) * DD;
    float* dst = g_base + (size_t)token * NDIM;
    for (int j = threadIdx.x; j < NDIM; j += 256) {
        int jj = (j & ~7) | invk(j & 7);
        int i = jj >> 10, dd = jj & 1023;
        dst[j] = f2tf_f(sp0[(size_t)i*TT*DD + dd] * s);
    }
}

// ---- phi weights pack (fold mhc norm), rounded + interleaved ----
__global__ void __launch_bounds__(256) k_pack(const float* __restrict__ mhc_norm_w,
                                              const float* __restrict__ pw,
                                              const float* __restrict__ ow,
                                              const float* __restrict__ rw)
{
    int base = blockIdx.x * 1024;
    #pragma unroll
    for (int u = 0; u < 4; u++) {
        int idx = base + u*256 + threadIdx.x;
        int e = idx / (24*NDIM), rem = idx - e*24*NDIM, r = rem >> 12, jd = rem & 4095;
        int j = (jd & ~7) | invk(jd & 7);
        float w;
        if (r < 4)      w = pw[((size_t)e*4 + r)*NDIM + j];
        else if (r < 8) w = ow[((size_t)e*4 + (r-4))*NDIM + j];
        else            w = rw[((size_t)e*16 + (r-8))*NDIM + j];
        g_phiW[idx] = f2tf_f(w * mhc_norm_w[(size_t)e*NDIM + j]);
    }
}

// ---- generic weight pack: rounded + interleaved + K pad ----
__global__ void __launch_bounds__(256) k_packw(const float* __restrict__ src,
                                               float* __restrict__ dst,
                                               int Kact, int Kpad, long total)
{
    long i0 = (long)blockIdx.x * 1024 + threadIdx.x;
    #pragma unroll
    for (int u = 0; u < 4; u++) {
        long idx = i0 + u*256;
        if (idx >= total) return;
        long r = idx / Kpad;
        int kd = (int)(idx - r * Kpad);
        int k = (kd & ~7) | invk(kd & 7);
        dst[idx] = (k < Kact) ? f2tf_f(src[r * Kact + k]) : 0.f;
    }
}

// ---- tf32 GEMM (R2 geometry, prerounded+interleaved operands) ----
// MODE 0 raw->Cf, 1 silu->Ci(intl), 2 sigm->Cf, 3 silu->Cf, 4 mulAux->Ci(intl+pad0), 5 mulAux->Cf
template <int MODE>
__global__ void __launch_bounds__(256, 2) k_gemm(
    const float* __restrict__ A, int lda,
    const float* __restrict__ W, int ldw, int Ntot, int KT,
    float* __restrict__ Cf, float* __restrict__ Ci, int ldc,
    const float* __restrict__ Aux, int ldaux, int cntOv)
{
    extern __shared__ float sm[];
    int e = blockIdx.z;
    int cnt = (cntOv >= 0) ? cntOv : g_cnt[e];
    int m0 = blockIdx.x * 128;
    if (m0 >= cnt) return;
    int n0 = blockIdx.y * 128;

    A += (size_t)e * CAP * lda;
    W += (size_t)e * Ntot * ldw;
    size_t co = (size_t)e * CAP * ldc;
    if (Cf) Cf += co;
    if (Ci) Ci += co;
    if (Aux) Aux += (size_t)e * CAP * ldaux;

    uint32_t sb = (uint32_t)__cvta_generic_to_shared(sm);
    int tid = threadIdx.x, warp = tid >> 5, lane = tid & 31;
    int wm = warp >> 1, wn = warp & 1;       // warp tile 32m x 64n
    int qr = lane >> 2, qc = lane & 3;

    float acc[2][8][4];
    #pragma unroll
    for (int mt = 0; mt < 2; mt++)
        #pragma unroll
        for (int nt = 0; nt < 8; nt++)
            #pragma unroll
            for (int q = 0; q < 4; q++) acc[mt][nt][q] = 0.f;

    auto load_stage = [&](int kt, int stg) {
        int k0 = kt * 32;
        #pragma unroll
        for (int s4 = 0; s4 < 4; s4++) {
            int f = tid + s4*256, r = f >> 3, c = f & 7;
            cp16(sb + ((stg*4608 + r*36 + c*4) << 2), A + (size_t)(m0 + r)*lda + k0 + c*4, true);
        }
        #pragma unroll
        for (int s4 = 0; s4 < 4; s4++) {
            int f = tid + s4*256, r = f >> 3, c = f & 7;
            bool pr = (n0 + r) < Ntot;
            const float* gp = W + (size_t)(n0 + r)*ldw + k0 + c*4;
            cp16(sb + ((9216 + stg*4608 + r*36 + c*4) << 2), pr ? gp : W, pr);
        }
        asm volatile("cp.async.commit_group;");
    };

    load_stage(0, 0);

    for (int kt = 0; kt < KT; kt++) {
        if (kt + 1 < KT) load_stage(kt + 1, (kt + 1) & 1);
        if (kt + 1 < KT) asm volatile("cp.async.wait_group 1;");
        else             asm volatile("cp.async.wait_group 0;");
        __syncthreads();

        int stg = kt & 1;
        const float* Asm = sm + stg * 4608;
        const float* Bsm = sm + 9216 + stg * 4608;

        #pragma unroll
        for (int ks = 0; ks < 4; ks++) {
            int kb = ks * 8 + qc * 2;
            const float* ap = Asm + (wm*32 + qr)*36 + kb;
            float2 a0 = *(const float2*)ap;
            float2 a1 = *(const float2*)(ap + 8*36);
            float2 a2 = *(const float2*)(ap + 16*36);
            float2 a3 = *(const float2*)(ap + 24*36);
            const float* bp = Bsm + (wn*64 + qr)*36 + kb;
            #pragma unroll
            for (int nt = 0; nt < 8; nt++) {
                float2 bb = *(const float2*)(bp + nt*8*36);
                uint32_t b0 = __float_as_uint(bb.x), b1 = __float_as_uint(bb.y);
                mma8(acc[0][nt], __float_as_uint(a0.x), __float_as_uint(a1.x),
                     __float_as_uint(a0.y), __float_as_uint(a1.y), b0, b1);
                mma8(acc[1][nt], __float_as_uint(a2.x), __float_as_uint(a3.x),
                     __float_as_uint(a2.y), __float_as_uint(a3.y), b0, b1);
            }
        }
        __syncthreads();
    }

    #pragma unroll
    for (int mt = 0; mt < 2; mt++) {
        #pragma unroll
        for (int nt = 0; nt < 8; nt++) {
            int n = n0 + wn*64 + nt*8 + qc*2;
            #pragma unroll
            for (int half = 0; half < 2; half++) {
                int m = m0 + wm*32 + mt*16 + qr + half*8;
                if (m >= cnt) continue;
                float v0 = acc[mt][nt][half*2], v1 = acc[mt][nt][half*2 + 1];
                size_t off = (size_t)m * ldc + n;
                if (MODE == 0) {
                    if (n < Ntot) { float2 s2 = {v0, v1}; *(float2*)(Cf + off) = s2; }
                } else if (MODE == 2) {
                    if (n < Ntot) {
                        float2 s2 = {1.f/(1.f+expf(-v0)), 1.f/(1.f+expf(-v1))};
                        *(float2*)(Cf + off) = s2;
                    }
                } else if (MODE == 3) {
                    if (n < Ntot) {
                        float2 s2 = {v0/(1.f+expf(-v0)), v1/(1.f+expf(-v1))};
                        *(float2*)(Cf + off) = s2;
                    }
                } else if (MODE == 5) {
                    if (n < Ntot) {
                        float2 s2 = {v0 * Aux[(size_t)m*ldaux + n], v1 * Aux[(size_t)m*ldaux + n + 1]};
                        *(float2*)(Cf + off) = s2;
                    }
                } else {  // 1, 4: interleaved tf32 outputs
                    size_t rowo = (size_t)m * ldc + (n & ~7);
                    int p0 = posk(n & 7), p1 = posk((n + 1) & 7);
                    if (n < Ntot) {
                        float x0, x1;
                        if (MODE == 1) { x0 = v0/(1.f+expf(-v0)); x1 = v1/(1.f+expf(-v1)); }
                        else { x0 = v0 * Aux[(size_t)m*ldaux + n]; x1 = v1 * Aux[(size_t)m*ldaux + n + 1]; }
                        Ci[rowo + p0] = f2tf_f(x0);
                        Ci[rowo + p1] = f2tf_f(x1);
                    } else if (MODE == 4 && n < ldc) {
                        Ci[rowo + p0] = 0.f;
                        Ci[rowo + p1] = 0.f;
                    }
                }
            }
        }
    }
}

// ---- per active pair: gates, sinkhorn, h, hn (rounded + interleaved) ----
__global__ void __launch_bounds__(128) k_hn(const float* __restrict__ stream,
                                            const float* __restrict__ b_pre,
                                            const float* __restrict__ b_post,
                                            const float* __restrict__ b_res,
                                            const float* __restrict__ alpha_pre,
                                            const float* __restrict__ alpha_post,
                                            const float* __restrict__ alpha_res,
                                            const float* __restrict__ sw_norm_w)
{
    int row = blockIdx.x, e = blockIdx.y;
    if (row >= g_cnt[e]) return;
    int token = g_tok[e*CAP + row], b = token / TT, t = token % TT, tid = threadIdx.x;
    __shared__ float hpre[NS], red2[4];

    if (tid == 0) {
        const float* d = g_dots + (size_t)token*384 + e*24;
        size_t slot = (size_t)e*CAP + row;
        float ap = alpha_pre[e], ao = alpha_post[e], ar = alpha_res[e];
        #pragma unroll
        for (int i = 0; i < NS; i++)
            hpre[i] = 1.f / (1.f + expf(-(ap*d[i] + b_pre[e*NS+i])));
        #pragma unroll
        for (int i = 0; i < NS; i++)
            g_Hpost[slot*NS+i] = 2.f / (1.f + expf(-(ao*d[4+i] + b_post[e*NS+i])));
        float M[16];
        #pragma unroll
        for (int k = 0; k < 16; k++) M[k] = expf(ar*d[8+k] + b_res[e*16+k]);
        for (int it = 0; it < 6; it++) {
            #pragma unroll
            for (int i = 0; i < 4; i++) {
                float ir = 1.f / (M[i*4]+M[i*4+1]+M[i*4+2]+M[i*4+3]);
                M[i*4]*=ir; M[i*4+1]*=ir; M[i*4+2]*=ir; M[i*4+3]*=ir;
            }
            #pragma unroll
            for (int j = 0; j < 4; j++) {
                float ic = 1.f / (M[j]+M[4+j]+M[8+j]+M[12+j]);
                M[j]*=ic; M[4+j]*=ic; M[8+j]*=ic; M[12+j]*=ic;
            }
        }
        #pragma unroll
        for (int k = 0; k < 16; k++) g_Hres[slot*16+k] = M[k];
    }
    __syncthreads();

    const float* sp0 = stream + ((size_t)b*NS*TT + t) * DD;
    float h0 = hpre[0], h1 = hpre[1], h2 = hpre[2], h3 = hpre[3];
    float hreg[8], hq = 0.f;
    #pragma unroll
    for (int u = 0; u < 8; u++) {
        int dd = tid + u*128;
        float h = h0*sp0[dd] + h1*sp0[(size_t)TT*DD+dd]
                + h2*sp0[2*(size_t)TT*DD+dd] + h3*sp0[3*(size_t)TT*DD+dd];
        hreg[u] = h; hq += h*h;
    }
    int lane = tid & 31, warp = tid >> 5;
    #pragma unroll
    for (int o = 16; o > 0; o >>= 1) hq += __shfl_down_sync(0xffffffffu, hq, o);
    if (lane == 0) red2[warp] = hq;
    __syncthreads();
    if (tid == 0) red2[0] = rsqrtf((red2[0]+red2[1]+red2[2]+red2[3]) / (float)DD + EPS_F);
    __syncthreads();
    float sh = red2[0];
    const float* snw = sw_norm_w + (size_t)e*DD;
    float* hn = g_HN + ((size_t)e*CAP + row) * DD;
    #pragma unroll
    for (int u = 0; u < 8; u++) {
        int dd = tid + u*128;
        float v = hreg[u] * sh * snw[dd];
        hn[(dd & ~7) | posk(dd & 7)] = f2tf_f(v);
    }
}

// ---- combine res + post ----
__global__ void __launch_bounds__(128) k_out(const float* __restrict__ stream,
                                             float* __restrict__ outp)
{
    int token = blockIdx.x, b = token / TT, t = token % TT, tid = threadIdx.x;
    const float* sp0 = stream + ((size_t)b*NS*TT + t) * DD;
    float st[4][8], acc[4][8];
    #pragma unroll
    for (int i = 0; i < 4; i++)
        #pragma unroll
        for (int j = 0; j < 8; j++) {
            st[i][j] = sp0[(size_t)i*TT*DD + tid + j*128];
            acc[i][j] = 0.f;
        }
    for (int e = 0; e < EE; e++) {
        int row = g_row[token*EE + e];
        if (row < 0) continue;
        float g = g_gatev[token*EE + e];
        size_t slot = (size_t)e*CAP + row;
        float Hr[16], Hp[4];
        #pragma unroll
        for (int k = 0; k < 16; k++) Hr[k] = g_Hres[slot*16+k];
        #pragma unroll
        for (int i = 0; i < 4; i++) Hp[i] = g_Hpost[slot*4+i];
        const float* o = g_OUT + slot*DD;
        #pragma unroll
        for (int j = 0; j < 8; j++) {
            float ov = o[tid + j*128];
            #pragma unroll
            for (int i = 0; i < 4; i++) {
                float r = Hr[i*4]*st[0][j] + Hr[i*4+1]*st[1][j]
                        + Hr[i*4+2]*st[2][j] + Hr[i*4+3]*st[3][j];
                acc[i][j] += g * (r + Hp[i]*ov);
            }
        }
    }
    #pragma unroll
    for (int i = 0; i < 4; i++)
        #pragma unroll
        for (int j = 0; j < 8; j++)
            outp[((size_t)(b*NS+i)*TT + t)*DD + tid + j*128] = acc[i][j];
}

#define GSA(p, s) cudaGetSymbolAddress((void**)&p, s)

extern "C" void kernel_launch(void* const* d_in, const int* in_sizes, int n_in,
                              void* d_out, int out_size)
{
    (void)in_sizes; (void)n_in; (void)out_size;
    const float* stream   = (const float*)d_in[0];
    const float* router_w = (const float*)d_in[1];
    const float* mhc      = (const float*)d_in[2];
    const float* phi_pre  = (const float*)d_in[3];
    const float* phi_post = (const float*)d_in[4];
    const float* phi_res  = (const float*)d_in[5];
    const float* b_pre    = (const float*)d_in[6];
    const float* b_post   = (const float*)d_in[7];
    const float* b_res    = (const float*)d_in[8];
    const float* a_pre    = (const float*)d_in[9];
    const float* a_post   = (const float*)d_in[10];
    const float* a_res    = (const float*)d_in[11];
    const float* sw_nw    = (const float*)d_in[12];
    const float* wd_w     = (const float*)d_in[13];
    const float* wu_w     = (const float*)d_in[14];
    const float* gate_w   = (const float*)d_in[15];
    const float* up_w     = (const float*)d_in[16];
    const float* down_w   = (const float*)d_in[17];

    float* outp = (float*)d_out;
    float* out_gate = outp + (size_t)BB*NS*TT*DD;

    cudaFuncSetAttribute(k_gemm<0>, cudaFuncAttributeMaxDynamicSharedMemorySize, SMEM_DYN);
    cudaFuncSetAttribute(k_gemm<1>, cudaFuncAttributeMaxDynamicSharedMemorySize, SMEM_DYN);
    cudaFuncSetAttribute(k_gemm<2>, cudaFuncAttributeMaxDynamicSharedMemorySize, SMEM_DYN);
    cudaFuncSetAttribute(k_gemm<3>, cudaFuncAttributeMaxDynamicSharedMemorySize, SMEM_DYN);
    cudaFuncSetAttribute(k_gemm<4>, cudaFuncAttributeMaxDynamicSharedMemorySize, SMEM_DYN);
    cudaFuncSetAttribute(k_gemm<5>, cudaFuncAttributeMaxDynamicSharedMemorySize, SMEM_DYN);

    float *base, *HN, *T1, *GS, *P1, *P2, *OUT, *dots, *phiW, *wd, *wu, *gt, *up, *dn;
    GSA(base, g_base); GSA(HN, g_HN); GSA(T1, g_T1); GSA(GS, g_GS);
    GSA(P1, g_P1); GSA(P2, g_P2); GSA(OUT, g_OUT); GSA(dots, g_dots);
    GSA(phiW, g_phiW); GSA(wd, g_wd); GSA(wu, g_wu); GSA(gt, g_gt);
    GSA(up, g_up); GSA(dn, g_dn);

    k_zero<<<1, 32>>>();
    k_gate<<<BT, 256>>>(stream, router_w, out_gate);
    k_base<<<BT, 256>>>(stream);
    k_pack<<<(EE*24*NDIM)/1024, 256>>>(mhc, phi_pre, phi_post, phi_res);
    {
        long t1 = (long)EE*DD*DD, t2 = (long)EE*DFFN*DD, t3 = (long)EE*DD*LDP;
        k_packw<<<(unsigned)((t1+1023)/1024), 256>>>(wd_w,   wd, DD, DD, t1);
        k_packw<<<(unsigned)((t1+1023)/1024), 256>>>(wu_w,   wu, DD, DD, t1);
        k_packw<<<(unsigned)((t2+1023)/1024), 256>>>(gate_w, gt, DD, DD, t2);
        k_packw<<<(unsigned)((t2+1023)/1024), 256>>>(up_w,   up, DD, DD, t2);
        k_packw<<<(unsigned)((t3+1023)/1024), 256>>>(down_w, dn, DFFN, LDP, t3);
    }

    // dots = base @ phiW^T  (N=384, K=4096)
    k_gemm<0><<<dim3(32,3,1), 256, SMEM_DYN>>>(base, NDIM, phiW, NDIM, 384, NDIM/32,
                                               dots, (float*)0, 384, (const float*)0, 0, BT);

    k_hn<<<dim3(CAP, EE), 128>>>(stream, b_pre, b_post, b_res, a_pre, a_post, a_res, sw_nw);

    dim3 gD(32, 8, EE);    // N = 1024
    dim3 gF(32, 13, EE);   // N = 1656

    // T1 = silu(HN @ wd^T) -> interleaved tf32
    k_gemm<1><<<gD, 256, SMEM_DYN>>>(HN, DD, wd, DD, DD, DD/32,
                                     (float*)0, T1, DD, (const float*)0, 0, -1);
    // GS = sigmoid(T1 @ wu^T) -> f32
    k_gemm<2><<<gD, 256, SMEM_DYN>>>(T1, DD, wu, DD, DD, DD/32,
                                     GS, (float*)0, DD, (const float*)0, 0, -1);
    // P1 = silu(HN @ gate^T) -> f32 (ld LDP)
    k_gemm<3><<<gF, 256, SMEM_DYN>>>(HN, DD, gt, DD, DFFN, DD/32,
                                     P1, (float*)0, LDP, (const float*)0, 0, -1);
    // P2 = (HN @ up^T) * P1 -> interleaved tf32, zero-padded to LDP
    k_gemm<4><<<gF, 256, SMEM_DYN>>>(HN, DD, up, DD, DFFN, DD/32,
                                     (float*)0, P2, LDP, P1, LDP, -1);
    // OUT = (P2 @ dn^T) * GS -> f32
    k_gemm<5><<<gD, 256, SMEM_DYN>>>(P2, LDP, dn, LDP, DD, LDP/32,
                                     OUT, (float*)0, DD, GS, DD, -1);

    k_out<<<BT, 128>>>(stream, outp);
}

// round 7
// speedup vs baseline: 1.3361x; 1.1558x over previous
#include <cuda_runtime.h>
#include <math.h>
#include <stdint.h>

#define BB 2
#define NS 4
#define TT 2048
#define DD 1024
#define EE 16
#define NDIM 4096
#define DFFN 1656
#define LDP 1664
#define BT (BB*TT)
#define CAP BT
#define EPS_F 1.1920929e-7f
#define RS 40                    // smem row stride in floats (160B: conflict-free LDS.64)
#define STGF (256*RS)            // floats per stage (128 A rows + 128 B rows)
#define SMEM_DYN (2*STGF*4)      // 81920 B

// ---- device scratch ----
__device__ __align__(16) float g_base[(size_t)BT*NDIM];
__device__ __align__(16) float g_HN [(size_t)EE*CAP*DD];
__device__ __align__(16) float g_T1 [(size_t)EE*CAP*DD];
__device__ __align__(16) float g_GS [(size_t)EE*CAP*DD];
__device__ __align__(16) float g_P1 [(size_t)EE*CAP*LDP];
__device__ __align__(16) float g_P2 [(size_t)EE*CAP*LDP];
__device__ __align__(16) float g_OUT[(size_t)EE*CAP*DD];
__device__ __align__(16) float g_dots[(size_t)BT*384];
__device__ __align__(16) float g_phiW[(size_t)EE*24*NDIM];
__device__ __align__(16) float g_wd[(size_t)EE*DD*DD];
__device__ __align__(16) float g_wu[(size_t)EE*DD*DD];
__device__ __align__(16) float g_gt[(size_t)EE*DFFN*DD];
__device__ __align__(16) float g_up[(size_t)EE*DFFN*DD];
__device__ __align__(16) float g_dn[(size_t)EE*DD*LDP];
__device__ float g_srms[BT];
__device__ int   g_row[BT*EE];
__device__ float g_gatev[BT*EE];
__device__ int   g_tok[EE*CAP];
__device__ int   g_cnt[EE];
__device__ float g_Hpost[(size_t)EE*CAP*NS];
__device__ float g_Hres[(size_t)EE*CAP*16];

// ---- helpers ----
__device__ __forceinline__ float f2tf_f(float f) {
    uint32_t u;
    asm("cvt.rna.tf32.f32 %0, %1;" : "=r"(u) : "f"(f));
    return __uint_as_float(u);
}
__device__ __forceinline__ int posk(int k) { return ((k & 3) << 1) | ((k >> 2) & 1); }
__device__ __forceinline__ int invk(int p) { return ((p & 1) << 2) | (p >> 1); }
__device__ __forceinline__ void mma8(float* c, uint32_t a0, uint32_t a1, uint32_t a2,
                                     uint32_t a3, uint32_t b0, uint32_t b1) {
    asm volatile(
        "mma.sync.aligned.m16n8k8.row.col.f32.tf32.tf32.f32 "
        "{%0,%1,%2,%3}, {%4,%5,%6,%7}, {%8,%9}, {%0,%1,%2,%3};"
        : "+f"(c[0]), "+f"(c[1]), "+f"(c[2]), "+f"(c[3])
        : "r"(a0), "r"(a1), "r"(a2), "r"(a3), "r"(b0), "r"(b1));
}
__device__ __forceinline__ void cp16(uint32_t s, const void* g, bool pr) {
    int b = pr ? 16 : 0;
    asm volatile("cp.async.cg.shared.global [%0], [%1], 16, %2;" :: "r"(s), "l"(g), "r"(b));
}

__global__ void k_zero() { if (threadIdx.x < EE) g_cnt[threadIdx.x] = 0; }

// ---- router gate + token rms ----
__global__ void __launch_bounds__(256) k_gate(const float* __restrict__ stream,
                                              const float* __restrict__ router_w,
                                              float* __restrict__ out_gate)
{
    int token = blockIdx.x, b = token / TT, t = token % TT, tid = threadIdx.x;
    __shared__ float route[DD], red[256], logit[EE];
    const float* sp0 = stream + ((size_t)b * NS * TT + t) * DD;
    float ss = 0.f;
    for (int dd = tid; dd < DD; dd += 256) {
        float v0 = sp0[dd], v1 = sp0[(size_t)TT*DD + dd];
        float v2 = sp0[2*(size_t)TT*DD + dd], v3 = sp0[3*(size_t)TT*DD + dd];
        ss += v0*v0 + v1*v1 + v2*v2 + v3*v3;
        route[dd] = 0.25f * (v0 + v1 + v2 + v3);
    }
    red[tid] = ss; __syncthreads();
    for (int s = 128; s > 0; s >>= 1) { if (tid < s) red[tid] += red[tid+s]; __syncthreads(); }
    if (tid == 0) g_srms[token] = rsqrtf(red[0] / (float)NDIM + EPS_F);
    int warp = tid >> 5, lane = tid & 31;
    for (int e = warp; e < EE; e += 8) {
        const float* rw = router_w + (size_t)e * DD;
        float acc = 0.f;
        for (int dd = lane; dd < DD; dd += 32) acc += route[dd] * rw[dd];
        #pragma unroll
        for (int o = 16; o > 0; o >>= 1) acc += __shfl_down_sync(0xffffffffu, acc, o);
        if (lane == 0) logit[e] = acc;
    }
    __syncthreads();
    if (tid == 0) {
        float p[EE], mx = -1e30f;
        #pragma unroll
        for (int e = 0; e < EE; e++) mx = fmaxf(mx, logit[e]);
        float sum = 0.f;
        #pragma unroll
        for (int e = 0; e < EE; e++) { p[e] = expf(logit[e] - mx); sum += p[e]; }
        float inv = 1.f / sum;
        #pragma unroll
        for (int e = 0; e < EE; e++) p[e] *= inv;
        int ord[EE];
        #pragma unroll
        for (int e = 0; e < EE; e++) ord[e] = e;
        for (int i = 1; i < EE; i++) {
            int oi = ord[i]; float pi = p[oi]; int j = i - 1;
            while (j >= 0 && p[ord[j]] < pi) { ord[j+1] = ord[j]; j--; }
            ord[j+1] = oi;
        }
        float cum = 0.f, gate[EE];
        #pragma unroll
        for (int e = 0; e < EE; e++) gate[e] = 0.f;
        for (int r = 0; r < EE; r++) {
            int e = ord[r];
            if ((r == 0) || (cum < 0.8f && r < 4)) gate[e] = p[e];
            cum += p[e];
        }
        for (int e = 0; e < EE; e++) {
            float g = gate[e];
            out_gate[(size_t)token*EE + e] = g;
            g_gatev[token*EE + e] = g;
            int row = -1;
            if (g > 0.f) { row = atomicAdd(&g_cnt[e], 1); g_tok[e*CAP + row] = token; }
            g_row[token*EE + e] = row;
        }
    }
}

// ---- base: tf32-rounded + k-interleaved ----
__global__ void __launch_bounds__(256) k_base(const float* __restrict__ stream)
{
    int token = blockIdx.x, b = token / TT, t = token % TT;
    float s = g_srms[token];
    const float* sp0 = stream + ((size_t)b * NS * TT + t) * DD;
    float* dst = g_base + (size_t)token * NDIM;
    for (int j = threadIdx.x; j < NDIM; j += 256) {
        int jj = (j & ~7) | invk(j & 7);
        int i = jj >> 10, dd = jj & 1023;
        dst[j] = f2tf_f(sp0[(size_t)i*TT*DD + dd] * s);
    }
}

// ---- phi weights pack (fold mhc norm), rounded + interleaved ----
__global__ void __launch_bounds__(256) k_pack(const float* __restrict__ mhc_norm_w,
                                              const float* __restrict__ pw,
                                              const float* __restrict__ ow,
                                              const float* __restrict__ rw)
{
    int base = blockIdx.x * 1024;
    #pragma unroll
    for (int u = 0; u < 4; u++) {
        int idx = base + u*256 + threadIdx.x;
        int e = idx / (24*NDIM), rem = idx - e*24*NDIM, r = rem >> 12, jd = rem & 4095;
        int j = (jd & ~7) | invk(jd & 7);
        float w;
        if (r < 4)      w = pw[((size_t)e*4 + r)*NDIM + j];
        else if (r < 8) w = ow[((size_t)e*4 + (r-4))*NDIM + j];
        else            w = rw[((size_t)e*16 + (r-8))*NDIM + j];
        g_phiW[idx] = f2tf_f(w * mhc_norm_w[(size_t)e*NDIM + j]);
    }
}

// ---- generic weight pack: rounded + interleaved + K pad ----
__global__ void __launch_bounds__(256) k_packw(const float* __restrict__ src,
                                               float* __restrict__ dst,
                                               int Kact, int Kpad, long total)
{
    long i0 = (long)blockIdx.x * 1024 + threadIdx.x;
    #pragma unroll
    for (int u = 0; u < 4; u++) {
        long idx = i0 + u*256;
        if (idx >= total) return;
        long r = idx / Kpad;
        int kd = (int)(idx - r * Kpad);
        int k = (kd & ~7) | invk(kd & 7);
        dst[idx] = (k < Kact) ? f2tf_f(src[r * Kact + k]) : 0.f;
    }
}

// ---- tf32 GEMM (128x128 tile, conflict-free LDS.64, prerounded+interleaved) ----
// MODE 0 raw->Cf, 1 silu->Ci(intl), 2 sigm->Cf, 3 silu->Cf, 4 mulAux->Ci(intl+pad0), 5 mulAux->Cf
template <int MODE>
__global__ void __launch_bounds__(256, 2) k_gemm(
    const float* __restrict__ A, int lda,
    const float* __restrict__ W, int ldw, int Ntot, int KT,
    float* __restrict__ Cf, float* __restrict__ Ci, int ldc,
    const float* __restrict__ Aux, int ldaux, int cntOv)
{
    extern __shared__ float sm[];
    int e = blockIdx.z;
    int cnt = (cntOv >= 0) ? cntOv : g_cnt[e];
    int m0 = blockIdx.x * 128;
    if (m0 >= cnt) return;
    int n0 = blockIdx.y * 128;

    A += (size_t)e * CAP * lda;
    W += (size_t)e * Ntot * ldw;
    size_t co = (size_t)e * CAP * ldc;
    if (Cf) Cf += co;
    if (Ci) Ci += co;
    if (Aux) Aux += (size_t)e * CAP * ldaux;

    uint32_t sb = (uint32_t)__cvta_generic_to_shared(sm);
    int tid = threadIdx.x, warp = tid >> 5, lane = tid & 31;
    int wm = warp >> 1, wn = warp & 1;       // warp tile 32m x 64n
    int qr = lane >> 2, qc = lane & 3;

    float acc[2][8][4];
    #pragma unroll
    for (int mt = 0; mt < 2; mt++)
        #pragma unroll
        for (int nt = 0; nt < 8; nt++)
            #pragma unroll
            for (int q = 0; q < 4; q++) acc[mt][nt][q] = 0.f;

    auto load_stage = [&](int kt, int stg) {
        int k0 = kt * 32;
        #pragma unroll
        for (int s4 = 0; s4 < 4; s4++) {
            int f = tid + s4*256, r = f >> 3, c = f & 7;
            cp16(sb + ((stg*STGF + r*RS + c*4) << 2), A + (size_t)(m0 + r)*lda + k0 + c*4, true);
        }
        #pragma unroll
        for (int s4 = 0; s4 < 4; s4++) {
            int f = tid + s4*256, r = f >> 3, c = f & 7;
            bool pr = (n0 + r) < Ntot;
            const float* gp = W + (size_t)(n0 + r)*ldw + k0 + c*4;
            cp16(sb + ((stg*STGF + 128*RS + r*RS + c*4) << 2), pr ? gp : W, pr);
        }
        asm volatile("cp.async.commit_group;");
    };

    load_stage(0, 0);

    for (int kt = 0; kt < KT; kt++) {
        if (kt + 1 < KT) load_stage(kt + 1, (kt + 1) & 1);
        if (kt + 1 < KT) asm volatile("cp.async.wait_group 1;");
        else             asm volatile("cp.async.wait_group 0;");
        __syncthreads();

        int stg = kt & 1;
        const float* Asm = sm + stg * STGF;
        const float* Bsm = Asm + 128 * RS;

        #pragma unroll
        for (int ks = 0; ks < 4; ks++) {
            int kb = ks * 8 + qc * 2;
            const float* ap = Asm + (wm*32 + qr)*RS + kb;
            float2 a0 = *(const float2*)ap;
            float2 a1 = *(const float2*)(ap + 8*RS);
            float2 a2 = *(const float2*)(ap + 16*RS);
            float2 a3 = *(const float2*)(ap + 24*RS);
            const float* bp = Bsm + (wn*64 + qr)*RS + kb;
            #pragma unroll
            for (int nt = 0; nt < 8; nt++) {
                float2 bb = *(const float2*)(bp + nt*8*RS);
                uint32_t b0 = __float_as_uint(bb.x), b1 = __float_as_uint(bb.y);
                mma8(acc[0][nt], __float_as_uint(a0.x), __float_as_uint(a1.x),
                     __float_as_uint(a0.y), __float_as_uint(a1.y), b0, b1);
                mma8(acc[1][nt], __float_as_uint(a2.x), __float_as_uint(a3.x),
                     __float_as_uint(a2.y), __float_as_uint(a3.y), b0, b1);
            }
        }
        __syncthreads();
    }

    #pragma unroll
    for (int mt = 0; mt < 2; mt++) {
        #pragma unroll
        for (int nt = 0; nt < 8; nt++) {
            int n = n0 + wn*64 + nt*8 + qc*2;
            #pragma unroll
            for (int half = 0; half < 2; half++) {
                int m = m0 + wm*32 + mt*16 + qr + half*8;
                if (m >= cnt) continue;
                float v0 = acc[mt][nt][half*2], v1 = acc[mt][nt][half*2 + 1];
                size_t off = (size_t)m * ldc + n;
                if (MODE == 0) {
                    if (n < Ntot) { float2 s2 = {v0, v1}; *(float2*)(Cf + off) = s2; }
                } else if (MODE == 2) {
                    if (n < Ntot) {
                        float2 s2 = {1.f/(1.f+expf(-v0)), 1.f/(1.f+expf(-v1))};
                        *(float2*)(Cf + off) = s2;
                    }
                } else if (MODE == 3) {
                    if (n < Ntot) {
                        float2 s2 = {v0/(1.f+expf(-v0)), v1/(1.f+expf(-v1))};
                        *(float2*)(Cf + off) = s2;
                    }
                } else if (MODE == 5) {
                    if (n < Ntot) {
                        float2 s2 = {v0 * Aux[(size_t)m*ldaux + n], v1 * Aux[(size_t)m*ldaux + n + 1]};
                        *(float2*)(Cf + off) = s2;
                    }
                } else {  // 1, 4: interleaved tf32 outputs
                    size_t rowo = (size_t)m * ldc + (n & ~7);
                    int p0 = posk(n & 7), p1 = posk((n + 1) & 7);
                    if (n < Ntot) {
                        float x0, x1;
                        if (MODE == 1) { x0 = v0/(1.f+expf(-v0)); x1 = v1/(1.f+expf(-v1)); }
                        else { x0 = v0 * Aux[(size_t)m*ldaux + n]; x1 = v1 * Aux[(size_t)m*ldaux + n + 1]; }
                        Ci[rowo + p0] = f2tf_f(x0);
                        Ci[rowo + p1] = f2tf_f(x1);
                    } else if (MODE == 4 && n < ldc) {
                        Ci[rowo + p0] = 0.f;
                        Ci[rowo + p1] = 0.f;
                    }
                }
            }
        }
    }
}

// ---- per active pair: gates, sinkhorn, h, hn (rounded + interleaved) ----
__global__ void __launch_bounds__(128) k_hn(const float* __restrict__ stream,
                                            const float* __restrict__ b_pre,
                                            const float* __restrict__ b_post,
                                            const float* __restrict__ b_res,
                                            const float* __restrict__ alpha_pre,
                                            const float* __restrict__ alpha_post,
                                            const float* __restrict__ alpha_res,
                                            const float* __restrict__ sw_norm_w)
{
    int row = blockIdx.x, e = blockIdx.y;
    if (row >= g_cnt[e]) return;
    int token = g_tok[e*CAP + row], b = token / TT, t = token % TT, tid = threadIdx.x;
    __shared__ float hpre[NS], red2[4];

    if (tid == 0) {
        const float* d = g_dots + (size_t)token*384 + e*24;
        size_t slot = (size_t)e*CAP + row;
        float ap = alpha_pre[e], ao = alpha_post[e], ar = alpha_res[e];
        #pragma unroll
        for (int i = 0; i < NS; i++)
            hpre[i] = 1.f / (1.f + expf(-(ap*d[i] + b_pre[e*NS+i])));
        #pragma unroll
        for (int i = 0; i < NS; i++)
            g_Hpost[slot*NS+i] = 2.f / (1.f + expf(-(ao*d[4+i] + b_post[e*NS+i])));
        float M[16];
        #pragma unroll
        for (int k = 0; k < 16; k++) M[k] = expf(ar*d[8+k] + b_res[e*16+k]);
        for (int it = 0; it < 6; it++) {
            #pragma unroll
            for (int i = 0; i < 4; i++) {
                float ir = 1.f / (M[i*4]+M[i*4+1]+M[i*4+2]+M[i*4+3]);
                M[i*4]*=ir; M[i*4+1]*=ir; M[i*4+2]*=ir; M[i*4+3]*=ir;
            }
            #pragma unroll
            for (int j = 0; j < 4; j++) {
                float ic = 1.f / (M[j]+M[4+j]+M[8+j]+M[12+j]);
                M[j]*=ic; M[4+j]*=ic; M[8+j]*=ic; M[12+j]*=ic;
            }
        }
        #pragma unroll
        for (int k = 0; k < 16; k++) g_Hres[slot*16+k] = M[k];
    }
    __syncthreads();

    const float* sp0 = stream + ((size_t)b*NS*TT + t) * DD;
    float h0 = hpre[0], h1 = hpre[1], h2 = hpre[2], h3 = hpre[3];
    float hreg[8], hq = 0.f;
    #pragma unroll
    for (int u = 0; u < 8; u++) {
        int dd = tid + u*128;
        float h = h0*sp0[dd] + h1*sp0[(size_t)TT*DD+dd]
                + h2*sp0[2*(size_t)TT*DD+dd] + h3*sp0[3*(size_t)TT*DD+dd];
        hreg[u] = h; hq += h*h;
    }
    int lane = tid & 31, warp = tid >> 5;
    #pragma unroll
    for (int o = 16; o > 0; o >>= 1) hq += __shfl_down_sync(0xffffffffu, hq, o);
    if (lane == 0) red2[warp] = hq;
    __syncthreads();
    if (tid == 0) red2[0] = rsqrtf((red2[0]+red2[1]+red2[2]+red2[3]) / (float)DD + EPS_F);
    __syncthreads();
    float sh = red2[0];
    const float* snw = sw_norm_w + (size_t)e*DD;
    float* hn = g_HN + ((size_t)e*CAP + row) * DD;
    #pragma unroll
    for (int u = 0; u < 8; u++) {
        int dd = tid + u*128;
        float v = hreg[u] * sh * snw[dd];
        hn[(dd & ~7) | posk(dd & 7)] = f2tf_f(v);
    }
}

// ---- combine res + post ----
__global__ void __launch_bounds__(128) k_out(const float* __restrict__ stream,
                                             float* __restrict__ outp)
{
    int token = blockIdx.x, b = token / TT, t = token % TT, tid = threadIdx.x;
    const float* sp0 = stream + ((size_t)b*NS*TT + t) * DD;
    float st[4][8], acc[4][8];
    #pragma unroll
    for (int i = 0; i < 4; i++)
        #pragma unroll
        for (int j = 0; j < 8; j++) {
            st[i][j] = sp0[(size_t)i*TT*DD + tid + j*128];
            acc[i][j] = 0.f;
        }
    for (int e = 0; e < EE; e++) {
        int row = g_row[token*EE + e];
        if (row < 0) continue;
        float g = g_gatev[token*EE + e];
        size_t slot = (size_t)e*CAP + row;
        float Hr[16], Hp[4];
        #pragma unroll
        for (int k = 0; k < 16; k++) Hr[k] = g_Hres[slot*16+k];
        #pragma unroll
        for (int i = 0; i < 4; i++) Hp[i] = g_Hpost[slot*4+i];
        const float* o = g_OUT + slot*DD;
        #pragma unroll
        for (int j = 0; j < 8; j++) {
            float ov = o[tid + j*128];
            #pragma unroll
            for (int i = 0; i < 4; i++) {
                float r = Hr[i*4]*st[0][j] + Hr[i*4+1]*st[1][j]
                        + Hr[i*4+2]*st[2][j] + Hr[i*4+3]*st[3][j];
                acc[i][j] += g * (r + Hp[i]*ov);
            }
        }
    }
    #pragma unroll
    for (int i = 0; i < 4; i++)
        #pragma unroll
        for (int j = 0; j < 8; j++)
            outp[((size_t)(b*NS+i)*TT + t)*DD + tid + j*128] = acc[i][j];
}

#define GSA(p, s) cudaGetSymbolAddress((void**)&p, s)

extern "C" void kernel_launch(void* const* d_in, const int* in_sizes, int n_in,
                              void* d_out, int out_size)
{
    (void)in_sizes; (void)n_in; (void)out_size;
    const float* stream   = (const float*)d_in[0];
    const float* router_w = (const float*)d_in[1];
    const float* mhc      = (const float*)d_in[2];
    const float* phi_pre  = (const float*)d_in[3];
    const float* phi_post = (const float*)d_in[4];
    const float* phi_res  = (const float*)d_in[5];
    const float* b_pre    = (const float*)d_in[6];
    const float* b_post   = (const float*)d_in[7];
    const float* b_res    = (const float*)d_in[8];
    const float* a_pre    = (const float*)d_in[9];
    const float* a_post   = (const float*)d_in[10];
    const float* a_res    = (const float*)d_in[11];
    const float* sw_nw    = (const float*)d_in[12];
    const float* wd_w     = (const float*)d_in[13];
    const float* wu_w     = (const float*)d_in[14];
    const float* gate_w   = (const float*)d_in[15];
    const float* up_w     = (const float*)d_in[16];
    const float* down_w   = (const float*)d_in[17];

    float* outp = (float*)d_out;
    float* out_gate = outp + (size_t)BB*NS*TT*DD;

    cudaFuncSetAttribute(k_gemm<0>, cudaFuncAttributeMaxDynamicSharedMemorySize, SMEM_DYN);
    cudaFuncSetAttribute(k_gemm<1>, cudaFuncAttributeMaxDynamicSharedMemorySize, SMEM_DYN);
    cudaFuncSetAttribute(k_gemm<2>, cudaFuncAttributeMaxDynamicSharedMemorySize, SMEM_DYN);
    cudaFuncSetAttribute(k_gemm<3>, cudaFuncAttributeMaxDynamicSharedMemorySize, SMEM_DYN);
    cudaFuncSetAttribute(k_gemm<4>, cudaFuncAttributeMaxDynamicSharedMemorySize, SMEM_DYN);
    cudaFuncSetAttribute(k_gemm<5>, cudaFuncAttributeMaxDynamicSharedMemorySize, SMEM_DYN);

    float *base, *HN, *T1, *GS, *P1, *P2, *OUT, *dots, *phiW, *wd, *wu, *gt, *up, *dn;
    GSA(base, g_base); GSA(HN, g_HN); GSA(T1, g_T1); GSA(GS, g_GS);
    GSA(P1, g_P1); GSA(P2, g_P2); GSA(OUT, g_OUT); GSA(dots, g_dots);
    GSA(phiW, g_phiW); GSA(wd, g_wd); GSA(wu, g_wu); GSA(gt, g_gt);
    GSA(up, g_up); GSA(dn, g_dn);

    k_zero<<<1, 32>>>();
    k_gate<<<BT, 256>>>(stream, router_w, out_gate);
    k_base<<<BT, 256>>>(stream);
    k_pack<<<(EE*24*NDIM)/1024, 256>>>(mhc, phi_pre, phi_post, phi_res);
    {
        long t1 = (long)EE*DD*DD, t2 = (long)EE*DFFN*DD, t3 = (long)EE*DD*LDP;
        k_packw<<<(unsigned)((t1+1023)/1024), 256>>>(wd_w,   wd, DD, DD, t1);
        k_packw<<<(unsigned)((t1+1023)/1024), 256>>>(wu_w,   wu, DD, DD, t1);
        k_packw<<<(unsigned)((t2+1023)/1024), 256>>>(gate_w, gt, DD, DD, t2);
        k_packw<<<(unsigned)((t2+1023)/1024), 256>>>(up_w,   up, DD, DD, t2);
        k_packw<<<(unsigned)((t3+1023)/1024), 256>>>(down_w, dn, DFFN, LDP, t3);
    }

    // dots = base @ phiW^T  (N=384, K=4096)
    k_gemm<0><<<dim3(32,3,1), 256, SMEM_DYN>>>(base, NDIM, phiW, NDIM, 384, NDIM/32,
                                               dots, (float*)0, 384, (const float*)0, 0, BT);

    k_hn<<<dim3(CAP, EE), 128>>>(stream, b_pre, b_post, b_res, a_pre, a_post, a_res, sw_nw);

    dim3 gD(32, 8, EE);    // N = 1024
    dim3 gF(32, 13, EE);   // N = 1656

    // T1 = silu(HN @ wd^T) -> interleaved tf32
    k_gemm<1><<<gD, 256, SMEM_DYN>>>(HN, DD, wd, DD, DD, DD/32,
                                     (float*)0, T1, DD, (const float*)0, 0, -1);
    // GS = sigmoid(T1 @ wu^T) -> f32
    k_gemm<2><<<gD, 256, SMEM_DYN>>>(T1, DD, wu, DD, DD, DD/32,
                                     GS, (float*)0, DD, (const float*)0, 0, -1);
    // P1 = silu(HN @ gate^T) -> f32 (ld LDP)
    k_gemm<3><<<gF, 256, SMEM_DYN>>>(HN, DD, gt, DD, DFFN, DD/32,
                                     P1, (float*)0, LDP, (const float*)0, 0, -1);
    // P2 = (HN @ up^T) * P1 -> interleaved tf32, zero-padded to LDP
    k_gemm<4><<<gF, 256, SMEM_DYN>>>(HN, DD, up, DD, DFFN, DD/32,
                                     (float*)0, P2, LDP, P1, LDP, -1);
    // OUT = (P2 @ dn^T) * GS -> f32
    k_gemm<5><<<gD, 256, SMEM_DYN>>>(P2, LDP, dn, LDP, DD, LDP/32,
                                     OUT, (float*)0, DD, GS, DD, -1);

    k_out<<<BT, 128>>>(stream, outp);
}

// round 9
// speedup vs baseline: 1.4374x; 1.0758x over previous
#include <cuda_runtime.h>
#include <math.h>
#include <stdint.h>

#define BB 2
#define NS 4
#define TT 2048
#define DD 1024
#define EE 16
#define NDIM 4096
#define DFFN 1656
#define LDP 1664
#define BT (BB*TT)
#define CAP BT
#define EPS_F 1.1920929e-7f
#define RS 40
#define STGF (256*RS)
#define SMEM_DYN (2*STGF*4)

// ---- device scratch ----
__device__ __align__(16) float g_base[(size_t)BT*NDIM];
__device__ __align__(16) float g_HN [(size_t)EE*CAP*DD];
__device__ __align__(16) float g_T1 [(size_t)EE*CAP*DD];
__device__ __align__(16) float g_GS [(size_t)EE*CAP*DD];
__device__ __align__(16) float g_P1 [(size_t)EE*CAP*LDP];
__device__ __align__(16) float g_P2 [(size_t)EE*CAP*LDP];
__device__ __align__(16) float g_OUT[(size_t)EE*CAP*DD];
__device__ __align__(16) float g_dots[(size_t)BT*384];
__device__ __align__(16) float g_phiW[(size_t)EE*24*NDIM];
__device__ __align__(16) float g_wd[(size_t)EE*DD*DD];
__device__ __align__(16) float g_wu[(size_t)EE*DD*DD];
__device__ __align__(16) float g_gt[(size_t)EE*DFFN*DD];
__device__ __align__(16) float g_up[(size_t)EE*DFFN*DD];
__device__ __align__(16) float g_dn[(size_t)EE*DD*LDP];
__device__ float g_srms[BT];
__device__ int   g_row[BT*EE];
__device__ float g_gatev[BT*EE];
__device__ int   g_tok[EE*CAP];
__device__ int   g_cnt[EE];
__device__ float g_Hpost[(size_t)EE*CAP*NS];
__device__ float g_Hres[(size_t)EE*CAP*16];

// ---- helpers ----
__device__ __forceinline__ float f2tf_f(float f) {
    uint32_t u;
    asm("cvt.rna.tf32.f32 %0, %1;" : "=r"(u) : "f"(f));
    return __uint_as_float(u);
}
__device__ __forceinline__ int posk(int k) { return ((k & 3) << 1) | ((k >> 2) & 1); }
__device__ __forceinline__ void perm8(const float* s, float4& o0, float4& o1) {
    // dst[posk(k)] = s[k]  =>  dst = {s0,s4,s1,s5,s2,s6,s3,s7}
    o0.x = f2tf_f(s[0]); o0.y = f2tf_f(s[4]); o0.z = f2tf_f(s[1]); o0.w = f2tf_f(s[5]);
    o1.x = f2tf_f(s[2]); o1.y = f2tf_f(s[6]); o1.z = f2tf_f(s[3]); o1.w = f2tf_f(s[7]);
}
__device__ __forceinline__ void mma8(float* c, uint32_t a0, uint32_t a1, uint32_t a2,
                                     uint32_t a3, uint32_t b0, uint32_t b1) {
    asm volatile(
        "mma.sync.aligned.m16n8k8.row.col.f32.tf32.tf32.f32 "
        "{%0,%1,%2,%3}, {%4,%5,%6,%7}, {%8,%9}, {%0,%1,%2,%3};"
        : "+f"(c[0]), "+f"(c[1]), "+f"(c[2]), "+f"(c[3])
        : "r"(a0), "r"(a1), "r"(a2), "r"(a3), "r"(b0), "r"(b1));
}
__device__ __forceinline__ void cp16(uint32_t s, const void* g, bool pr) {
    int b = pr ? 16 : 0;
    asm volatile("cp.async.cg.shared.global [%0], [%1], 16, %2;" :: "r"(s), "l"(g), "r"(b));
}

__global__ void k_zero() { if (threadIdx.x < EE) g_cnt[threadIdx.x] = 0; }

// ---- router gate + token rms ----
__global__ void __launch_bounds__(256) k_gate(const float* __restrict__ stream,
                                              const float* __restrict__ router_w,
                                              float* __restrict__ out_gate)
{
    int token = blockIdx.x, b = token / TT, t = token % TT, tid = threadIdx.x;
    __shared__ float route[DD], red[256], logit[EE];
    const float* sp0 = stream + ((size_t)b * NS * TT + t) * DD;
    float ss = 0.f;
    for (int dd = tid; dd < DD; dd += 256) {
        float v0 = sp0[dd], v1 = sp0[(size_t)TT*DD + dd];
        float v2 = sp0[2*(size_t)TT*DD + dd], v3 = sp0[3*(size_t)TT*DD + dd];
        ss += v0*v0 + v1*v1 + v2*v2 + v3*v3;
        route[dd] = 0.25f * (v0 + v1 + v2 + v3);
    }
    red[tid] = ss; __syncthreads();
    for (int s = 128; s > 0; s >>= 1) { if (tid < s) red[tid] += red[tid+s]; __syncthreads(); }
    if (tid == 0) g_srms[token] = rsqrtf(red[0] / (float)NDIM + EPS_F);
    int warp = tid >> 5, lane = tid & 31;
    for (int e = warp; e < EE; e += 8) {
        const float* rw = router_w + (size_t)e * DD;
        float acc = 0.f;
        for (int dd = lane; dd < DD; dd += 32) acc += route[dd] * rw[dd];
        #pragma unroll
        for (int o = 16; o > 0; o >>= 1) acc += __shfl_down_sync(0xffffffffu, acc, o);
        if (lane == 0) logit[e] = acc;
    }
    __syncthreads();
    if (tid == 0) {
        float p[EE], mx = -1e30f;
        #pragma unroll
        for (int e = 0; e < EE; e++) mx = fmaxf(mx, logit[e]);
        float sum = 0.f;
        #pragma unroll
        for (int e = 0; e < EE; e++) { p[e] = expf(logit[e] - mx); sum += p[e]; }
        float inv = 1.f / sum;
        #pragma unroll
        for (int e = 0; e < EE; e++) p[e] *= inv;
        int ord[EE];
        #pragma unroll
        for (int e = 0; e < EE; e++) ord[e] = e;
        for (int i = 1; i < EE; i++) {
            int oi = ord[i]; float pi = p[oi]; int j = i - 1;
            while (j >= 0 && p[ord[j]] < pi) { ord[j+1] = ord[j]; j--; }
            ord[j+1] = oi;
        }
        float cum = 0.f, gate[EE];
        #pragma unroll
        for (int e = 0; e < EE; e++) gate[e] = 0.f;
        for (int r = 0; r < EE; r++) {
            int e = ord[r];
            if ((r == 0) || (cum < 0.8f && r < 4)) gate[e] = p[e];
            cum += p[e];
        }
        for (int e = 0; e < EE; e++) {
            float g = gate[e];
            out_gate[(size_t)token*EE + e] = g;
            g_gatev[token*EE + e] = g;
            int row = -1;
            if (g > 0.f) { row = atomicAdd(&g_cnt[e], 1); g_tok[e*CAP + row] = token; }
            g_row[token*EE + e] = row;
        }
    }
}

// ---- base: vectorized, tf32-rounded + k-interleaved ----
__global__ void __launch_bounds__(256) k_base(const float* __restrict__ stream)
{
    int token = blockIdx.x, b = token / TT, t = token % TT;
    float s = g_srms[token];
    const float* sp0 = stream + ((size_t)b * NS * TT + t) * DD;
    float* dst = g_base + (size_t)token * NDIM;
    #pragma unroll
    for (int u = 0; u < 2; u++) {
        int g = threadIdx.x + u * 256;
        int j0 = g * 8, i = j0 >> 10, dd0 = j0 & 1023;
        const float* p = sp0 + (size_t)i * TT * DD + dd0;
        float4 lo = *(const float4*)p, hi = *(const float4*)(p + 4);
        float sv[8] = {lo.x*s, lo.y*s, lo.z*s, lo.w*s, hi.x*s, hi.y*s, hi.z*s, hi.w*s};
        float4 o0, o1; perm8(sv, o0, o1);
        *(float4*)(dst + j0) = o0; *(float4*)(dst + j0 + 4) = o1;
    }
}

// ---- phi weights pack (fold mhc norm), vectorized; 12288 groups/expert ----
__global__ void __launch_bounds__(256) k_pack(const float* __restrict__ mhc_norm_w,
                                              const float* __restrict__ pw,
                                              const float* __restrict__ ow,
                                              const float* __restrict__ rw)
{
    int g = blockIdx.x * 256 + threadIdx.x;
    int e = g / 12288;               // 24*NDIM/8 = 12288 groups per expert (FIXED)
    int rem = g - e * 12288;
    int r = rem >> 9;                // 512 groups per row (NDIM/8)
    int j0 = (rem & 511) * 8;
    const float* wsrc;
    if (r < 4)      wsrc = pw + ((size_t)e*4 + r)*NDIM + j0;
    else if (r < 8) wsrc = ow + ((size_t)e*4 + (r-4))*NDIM + j0;
    else            wsrc = rw + ((size_t)e*16 + (r-8))*NDIM + j0;
    const float* nsrc = mhc_norm_w + (size_t)e*NDIM + j0;
    float4 w0 = *(const float4*)wsrc, w1 = *(const float4*)(wsrc + 4);
    float4 n0 = *(const float4*)nsrc, n1 = *(const float4*)(nsrc + 4);
    float sv[8] = {w0.x*n0.x, w0.y*n0.y, w0.z*n0.z, w0.w*n0.w,
                   w1.x*n1.x, w1.y*n1.y, w1.z*n1.z, w1.w*n1.w};
    float4 o0, o1; perm8(sv, o0, o1);
    float* q = g_phiW + (size_t)g * 8;
    *(float4*)q = o0; *(float4*)(q + 4) = o1;
}

// ---- weight pack: compile-time strides, vectorized, grid-stride ----
template <int KACT, int KPAD>
__global__ void __launch_bounds__(256) k_packw8(const float* __restrict__ src,
                                                float* __restrict__ dst, long ngroups)
{
    constexpr int GPR = KPAD / 8;
    long g0 = (long)blockIdx.x * 256 + threadIdx.x;
    long stride = (long)gridDim.x * 256;
    for (long g = g0; g < ngroups; g += stride) {
        long row = g / GPR;
        int gi = (int)(g - row * GPR);
        float4 o0, o1;
        if (gi * 8 + 8 <= KACT) {
            const float* p = src + row * KACT + gi * 8;
            float4 lo = *(const float4*)p, hi = *(const float4*)(p + 4);
            float sv[8] = {lo.x, lo.y, lo.z, lo.w, hi.x, hi.y, hi.z, hi.w};
            perm8(sv, o0, o1);
        } else {
            o0 = make_float4(0.f, 0.f, 0.f, 0.f); o1 = o0;
        }
        float* q = dst + g * 8;
        *(float4*)q = o0; *(float4*)(q + 4) = o1;
    }
}

// ---- tf32 GEMM (unchanged from R7) ----
template <int MODE>
__global__ void __launch_bounds__(256, 2) k_gemm(
    const float* __restrict__ A, int lda,
    const float* __restrict__ W, int ldw, int Ntot, int KT,
    float* __restrict__ Cf, float* __restrict__ Ci, int ldc,
    const float* __restrict__ Aux, int ldaux, int cntOv)
{
    extern __shared__ float sm[];
    int e = blockIdx.z;
    int cnt = (cntOv >= 0) ? cntOv : g_cnt[e];
    int m0 = blockIdx.x * 128;
    if (m0 >= cnt) return;
    int n0 = blockIdx.y * 128;

    A += (size_t)e * CAP * lda;
    W += (size_t)e * Ntot * ldw;
    size_t co = (size_t)e * CAP * ldc;
    if (Cf) Cf += co;
    if (Ci) Ci += co;
    if (Aux) Aux += (size_t)e * CAP * ldaux;

    uint32_t sb = (uint32_t)__cvta_generic_to_shared(sm);
    int tid = threadIdx.x, warp = tid >> 5, lane = tid & 31;
    int wm = warp >> 1, wn = warp & 1;
    int qr = lane >> 2, qc = lane & 3;

    float acc[2][8][4];
    #pragma unroll
    for (int mt = 0; mt < 2; mt++)
        #pragma unroll
        for (int nt = 0; nt < 8; nt++)
            #pragma unroll
            for (int q = 0; q < 4; q++) acc[mt][nt][q] = 0.f;

    auto load_stage = [&](int kt, int stg) {
        int k0 = kt * 32;
        #pragma unroll
        for (int s4 = 0; s4 < 4; s4++) {
            int f = tid + s4*256, r = f >> 3, c = f & 7;
            cp16(sb + ((stg*STGF + r*RS + c*4) << 2), A + (size_t)(m0 + r)*lda + k0 + c*4, true);
        }
        #pragma unroll
        for (int s4 = 0; s4 < 4; s4++) {
            int f = tid + s4*256, r = f >> 3, c = f & 7;
            bool pr = (n0 + r) < Ntot;
            const float* gp = W + (size_t)(n0 + r)*ldw + k0 + c*4;
            cp16(sb + ((stg*STGF + 128*RS + r*RS + c*4) << 2), pr ? gp : W, pr);
        }
        asm volatile("cp.async.commit_group;");
    };

    load_stage(0, 0);

    for (int kt = 0; kt < KT; kt++) {
        if (kt + 1 < KT) load_stage(kt + 1, (kt + 1) & 1);
        if (kt + 1 < KT) asm volatile("cp.async.wait_group 1;");
        else             asm volatile("cp.async.wait_group 0;");
        __syncthreads();

        int stg = kt & 1;
        const float* Asm = sm + stg * STGF;
        const float* Bsm = Asm + 128 * RS;

        #pragma unroll
        for (int ks = 0; ks < 4; ks++) {
            int kb = ks * 8 + qc * 2;
            const float* ap = Asm + (wm*32 + qr)*RS + kb;
            float2 a0 = *(const float2*)ap;
            float2 a1 = *(const float2*)(ap + 8*RS);
            float2 a2 = *(const float2*)(ap + 16*RS);
            float2 a3 = *(const float2*)(ap + 24*RS);
            const float* bp = Bsm + (wn*64 + qr)*RS + kb;
            #pragma unroll
            for (int nt = 0; nt < 8; nt++) {
                float2 bb = *(const float2*)(bp + nt*8*RS);
                uint32_t b0 = __float_as_uint(bb.x), b1 = __float_as_uint(bb.y);
                mma8(acc[0][nt], __float_as_uint(a0.x), __float_as_uint(a1.x),
                     __float_as_uint(a0.y), __float_as_uint(a1.y), b0, b1);
                mma8(acc[1][nt], __float_as_uint(a2.x), __float_as_uint(a3.x),
                     __float_as_uint(a2.y), __float_as_uint(a3.y), b0, b1);
            }
        }
        __syncthreads();
    }

    #pragma unroll
    for (int mt = 0; mt < 2; mt++) {
        #pragma unroll
        for (int nt = 0; nt < 8; nt++) {
            int n = n0 + wn*64 + nt*8 + qc*2;
            #pragma unroll
            for (int half = 0; half < 2; half++) {
                int m = m0 + wm*32 + mt*16 + qr + half*8;
                if (m >= cnt) continue;
                float v0 = acc[mt][nt][half*2], v1 = acc[mt][nt][half*2 + 1];
                size_t off = (size_t)m * ldc + n;
                if (MODE == 0) {
                    if (n < Ntot) { float2 s2 = {v0, v1}; *(float2*)(Cf + off) = s2; }
                } else if (MODE == 2) {
                    if (n < Ntot) {
                        float2 s2 = {1.f/(1.f+expf(-v0)), 1.f/(1.f+expf(-v1))};
                        *(float2*)(Cf + off) = s2;
                    }
                } else if (MODE == 3) {
                    if (n < Ntot) {
                        float2 s2 = {v0/(1.f+expf(-v0)), v1/(1.f+expf(-v1))};
                        *(float2*)(Cf + off) = s2;
                    }
                } else if (MODE == 5) {
                    if (n < Ntot) {
                        float2 s2 = {v0 * Aux[(size_t)m*ldaux + n], v1 * Aux[(size_t)m*ldaux + n + 1]};
                        *(float2*)(Cf + off) = s2;
                    }
                } else {
                    size_t rowo = (size_t)m * ldc + (n & ~7);
                    int p0 = posk(n & 7), p1 = posk((n + 1) & 7);
                    if (n < Ntot) {
                        float x0, x1;
                        if (MODE == 1) { x0 = v0/(1.f+expf(-v0)); x1 = v1/(1.f+expf(-v1)); }
                        else { x0 = v0 * Aux[(size_t)m*ldaux + n]; x1 = v1 * Aux[(size_t)m*ldaux + n + 1]; }
                        Ci[rowo + p0] = f2tf_f(x0);
                        Ci[rowo + p1] = f2tf_f(x1);
                    } else if (MODE == 4 && n < ldc) {
                        Ci[rowo + p0] = 0.f;
                        Ci[rowo + p1] = 0.f;
                    }
                }
            }
        }
    }
}

// ---- per active pair: gates, sinkhorn, h, hn ----
__global__ void __launch_bounds__(128) k_hn(const float* __restrict__ stream,
                                            const float* __restrict__ b_pre,
                                            const float* __restrict__ b_post,
                                            const float* __restrict__ b_res,
                                            const float* __restrict__ alpha_pre,
                                            const float* __restrict__ alpha_post,
                                            const float* __restrict__ alpha_res,
                                            const float* __restrict__ sw_norm_w)
{
    int row = blockIdx.x, e = blockIdx.y;
    if (row >= g_cnt[e]) return;
    int token = g_tok[e*CAP + row], b = token / TT, t = token % TT, tid = threadIdx.x;
    __shared__ float hpre[NS], red2[4];

    if (tid == 0) {
        const float* d = g_dots + (size_t)token*384 + e*24;
        size_t slot = (size_t)e*CAP + row;
        float ap = alpha_pre[e], ao = alpha_post[e], ar = alpha_res[e];
        #pragma unroll
        for (int i = 0; i < NS; i++)
            hpre[i] = 1.f / (1.f + expf(-(ap*d[i] + b_pre[e*NS+i])));
        #pragma unroll
        for (int i = 0; i < NS; i++)
            g_Hpost[slot*NS+i] = 2.f / (1.f + expf(-(ao*d[4+i] + b_post[e*NS+i])));
        float M[16];
        #pragma unroll
        for (int k = 0; k < 16; k++) M[k] = expf(ar*d[8+k] + b_res[e*16+k]);
        for (int it = 0; it < 6; it++) {
            #pragma unroll
            for (int i = 0; i < 4; i++) {
                float ir = 1.f / (M[i*4]+M[i*4+1]+M[i*4+2]+M[i*4+3]);
                M[i*4]*=ir; M[i*4+1]*=ir; M[i*4+2]*=ir; M[i*4+3]*=ir;
            }
            #pragma unroll
            for (int j = 0; j < 4; j++) {
                float ic = 1.f / (M[j]+M[4+j]+M[8+j]+M[12+j]);
                M[j]*=ic; M[4+j]*=ic; M[8+j]*=ic; M[12+j]*=ic;
            }
        }
        #pragma unroll
        for (int k = 0; k < 16; k++) g_Hres[slot*16+k] = M[k];
    }
    __syncthreads();

    const float* sp0 = stream + ((size_t)b*NS*TT + t) * DD;
    float h0 = hpre[0], h1 = hpre[1], h2 = hpre[2], h3 = hpre[3];
    float hreg[8], hq = 0.f;
    #pragma unroll
    for (int u = 0; u < 8; u++) {
        int dd = tid + u*128;
        float h = h0*sp0[dd] + h1*sp0[(size_t)TT*DD+dd]
                + h2*sp0[2*(size_t)TT*DD+dd] + h3*sp0[3*(size_t)TT*DD+dd];
        hreg[u] = h; hq += h*h;
    }
    int lane = tid & 31, warp = tid >> 5;
    #pragma unroll
    for (int o = 16; o > 0; o >>= 1) hq += __shfl_down_sync(0xffffffffu, hq, o);
    if (lane == 0) red2[warp] = hq;
    __syncthreads();
    if (tid == 0) red2[0] = rsqrtf((red2[0]+red2[1]+red2[2]+red2[3]) / (float)DD + EPS_F);
    __syncthreads();
    float sh = red2[0];
    const float* snw = sw_norm_w + (size_t)e*DD;
    float* hn = g_HN + ((size_t)e*CAP + row) * DD;
    #pragma unroll
    for (int u = 0; u < 8; u++) {
        int dd = tid + u*128;
        float v = hreg[u] * sh * snw[dd];
        hn[(dd & ~7) | posk(dd & 7)] = f2tf_f(v);
    }
}

// ---- combine res + post ----
__global__ void __launch_bounds__(128) k_out(const float* __restrict__ stream,
                                             float* __restrict__ outp)
{
    int token = blockIdx.x, b = token / TT, t = token % TT, tid = threadIdx.x;
    const float* sp0 = stream + ((size_t)b*NS*TT + t) * DD;
    float st[4][8], acc[4][8];
    #pragma unroll
    for (int i = 0; i < 4; i++)
        #pragma unroll
        for (int j = 0; j < 8; j++) {
            st[i][j] = sp0[(size_t)i*TT*DD + tid + j*128];
            acc[i][j] = 0.f;
        }
    for (int e = 0; e < EE; e++) {
        int row = g_row[token*EE + e];
        if (row < 0) continue;
        float g = g_gatev[token*EE + e];
        size_t slot = (size_t)e*CAP + row;
        float Hr[16], Hp[4];
        #pragma unroll
        for (int k = 0; k < 16; k++) Hr[k] = g_Hres[slot*16+k];
        #pragma unroll
        for (int i = 0; i < 4; i++) Hp[i] = g_Hpost[slot*4+i];
        const float* o = g_OUT + slot*DD;
        #pragma unroll
        for (int j = 0; j < 8; j++) {
            float ov = o[tid + j*128];
            #pragma unroll
            for (int i = 0; i < 4; i++) {
                float r = Hr[i*4]*st[0][j] + Hr[i*4+1]*st[1][j]
                        + Hr[i*4+2]*st[2][j] + Hr[i*4+3]*st[3][j];
                acc[i][j] += g * (r + Hp[i]*ov);
            }
        }
    }
    #pragma unroll
    for (int i = 0; i < 4; i++)
        #pragma unroll
        for (int j = 0; j < 8; j++)
            outp[((size_t)(b*NS+i)*TT + t)*DD + tid + j*128] = acc[i][j];
}

#define GSA(p, s) cudaGetSymbolAddress((void**)&p, s)

extern "C" void kernel_launch(void* const* d_in, const int* in_sizes, int n_in,
                              void* d_out, int out_size)
{
    (void)in_sizes; (void)n_in; (void)out_size;
    const float* stream   = (const float*)d_in[0];
    const float* router_w = (const float*)d_in[1];
    const float* mhc      = (const float*)d_in[2];
    const float* phi_pre  = (const float*)d_in[3];
    const float* phi_post = (const float*)d_in[4];
    const float* phi_res  = (const float*)d_in[5];
    const float* b_pre    = (const float*)d_in[6];
    const float* b_post   = (const float*)d_in[7];
    const float* b_res    = (const float*)d_in[8];
    const float* a_pre    = (const float*)d_in[9];
    const float* a_post   = (const float*)d_in[10];
    const float* a_res    = (const float*)d_in[11];
    const float* sw_nw    = (const float*)d_in[12];
    const float* wd_w     = (const float*)d_in[13];
    const float* wu_w     = (const float*)d_in[14];
    const float* gate_w   = (const float*)d_in[15];
    const float* up_w     = (const float*)d_in[16];
    const float* down_w   = (const float*)d_in[17];

    float* outp = (float*)d_out;
    float* out_gate = outp + (size_t)BB*NS*TT*DD;

    cudaFuncSetAttribute(k_gemm<0>, cudaFuncAttributeMaxDynamicSharedMemorySize, SMEM_DYN);
    cudaFuncSetAttribute(k_gemm<1>, cudaFuncAttributeMaxDynamicSharedMemorySize, SMEM_DYN);
    cudaFuncSetAttribute(k_gemm<2>, cudaFuncAttributeMaxDynamicSharedMemorySize, SMEM_DYN);
    cudaFuncSetAttribute(k_gemm<3>, cudaFuncAttributeMaxDynamicSharedMemorySize, SMEM_DYN);
    cudaFuncSetAttribute(k_gemm<4>, cudaFuncAttributeMaxDynamicSharedMemorySize, SMEM_DYN);
    cudaFuncSetAttribute(k_gemm<5>, cudaFuncAttributeMaxDynamicSharedMemorySize, SMEM_DYN);

    float *base, *HN, *T1, *GS, *P1, *P2, *OUT, *dots, *phiW, *wd, *wu, *gt, *up, *dn;
    GSA(base, g_base); GSA(HN, g_HN); GSA(T1, g_T1); GSA(GS, g_GS);
    GSA(P1, g_P1); GSA(P2, g_P2); GSA(OUT, g_OUT); GSA(dots, g_dots);
    GSA(phiW, g_phiW); GSA(wd, g_wd); GSA(wu, g_wu); GSA(gt, g_gt);
    GSA(up, g_up); GSA(dn, g_dn);

    k_zero<<<1, 32>>>();
    k_gate<<<BT, 256>>>(stream, router_w, out_gate);
    k_base<<<BT, 256>>>(stream);
    k_pack<<<(EE*24*NDIM/8)/256, 256>>>(mhc, phi_pre, phi_post, phi_res);
    {
        long n1 = (long)EE*DD*DD/8;
        long n2 = (long)EE*DFFN*DD/8;
        long n3 = (long)EE*DD*LDP/8;
        unsigned b1 = (unsigned)((n1 + 1023) / 1024);
        unsigned b2 = (unsigned)((n2 + 1023) / 1024);
        unsigned b3 = (unsigned)((n3 + 1023) / 1024);
        k_packw8<DD, DD><<<b1, 256>>>(wd_w, wd, n1);
        k_packw8<DD, DD><<<b1, 256>>>(wu_w, wu, n1);
        k_packw8<DD, DD><<<b2, 256>>>(gate_w, gt, n2);
        k_packw8<DD, DD><<<b2, 256>>>(up_w, up, n2);
        k_packw8<DFFN, LDP><<<b3, 256>>>(down_w, dn, n3);
    }

    // dots = base @ phiW^T  (N=384, K=4096)
    k_gemm<0><<<dim3(32,3,1), 256, SMEM_DYN>>>(base, NDIM, phiW, NDIM, 384, NDIM/32,
                                               dots, (float*)0, 384, (const float*)0, 0, BT);

    k_hn<<<dim3(CAP, EE), 128>>>(stream, b_pre, b_post, b_res, a_pre, a_post, a_res, sw_nw);

    dim3 gD(32, 8, EE);
    dim3 gF(32, 13, EE);

    k_gemm<1><<<gD, 256, SMEM_DYN>>>(HN, DD, wd, DD, DD, DD/32,
                                     (float*)0, T1, DD, (const float*)0, 0, -1);
    k_gemm<2><<<gD, 256, SMEM_DYN>>>(T1, DD, wu, DD, DD, DD/32,
                                     GS, (float*)0, DD, (const float*)0, 0, -1);
    k_gemm<3><<<gF, 256, SMEM_DYN>>>(HN, DD, gt, DD, DFFN, DD/32,
                                     P1, (float*)0, LDP, (const float*)0, 0, -1);
    k_gemm<4><<<gF, 256, SMEM_DYN>>>(HN, DD, up, DD, DFFN, DD/32,
                                     (float*)0, P2, LDP, P1, LDP, -1);
    k_gemm<5><<<gD, 256, SMEM_DYN>>>(P2, LDP, dn, LDP, DD, LDP/32,
                                     OUT, (float*)0, DD, GS, DD, -1);

    k_out<<<BT, 128>>>(stream, outp);
}

// round 10
// speedup vs baseline: 1.4775x; 1.0279x over previous
#include <cuda_runtime.h>
#include <math.h>
#include <stdint.h>

#define BB 2
#define NS 4
#define TT 2048
#define DD 1024
#define EE 16
#define NDIM 4096
#define DFFN 1656
#define LDP 1664
#define BT (BB*TT)
#define CAP BT
#define EPS_F 1.1920929e-7f
#define RS 40
#define STGF (256*RS)
#define SMEM_DYN (2*STGF*4)
#define STGFF (384*RS)
#define SMEM_F (2*STGFF*4)      // 122880 B

// ---- device scratch ----
__device__ __align__(16) float g_base[(size_t)BT*NDIM];
__device__ __align__(16) float g_HN [(size_t)EE*CAP*DD];
__device__ __align__(16) float g_T1 [(size_t)EE*CAP*DD];
__device__ __align__(16) float g_GS [(size_t)EE*CAP*DD];
__device__ __align__(16) float g_P2 [(size_t)EE*CAP*LDP];
__device__ __align__(16) float g_OUT[(size_t)EE*CAP*DD];
__device__ __align__(16) float g_dots[(size_t)BT*384];
__device__ __align__(16) float g_phiW[(size_t)EE*24*NDIM];
__device__ __align__(16) float g_wd[(size_t)EE*DD*DD];
__device__ __align__(16) float g_wu[(size_t)EE*DD*DD];
__device__ __align__(16) float g_gt[(size_t)EE*DFFN*DD];
__device__ __align__(16) float g_up[(size_t)EE*DFFN*DD];
__device__ __align__(16) float g_dn[(size_t)EE*DD*LDP];
__device__ float g_srms[BT];
__device__ int   g_row[BT*EE];
__device__ float g_gatev[BT*EE];
__device__ int   g_tok[EE*CAP];
__device__ int   g_cnt[EE];
__device__ float g_Hpost[(size_t)EE*CAP*NS];
__device__ float g_Hres[(size_t)EE*CAP*16];

// ---- helpers ----
__device__ __forceinline__ float f2tf_f(float f) {
    uint32_t u;
    asm("cvt.rna.tf32.f32 %0, %1;" : "=r"(u) : "f"(f));
    return __uint_as_float(u);
}
__device__ __forceinline__ int posk(int k) { return ((k & 3) << 1) | ((k >> 2) & 1); }
__device__ __forceinline__ void perm8(const float* s, float4& o0, float4& o1) {
    o0.x = f2tf_f(s[0]); o0.y = f2tf_f(s[4]); o0.z = f2tf_f(s[1]); o0.w = f2tf_f(s[5]);
    o1.x = f2tf_f(s[2]); o1.y = f2tf_f(s[6]); o1.z = f2tf_f(s[3]); o1.w = f2tf_f(s[7]);
}
__device__ __forceinline__ void mma8(float* c, uint32_t a0, uint32_t a1, uint32_t a2,
                                     uint32_t a3, uint32_t b0, uint32_t b1) {
    asm volatile(
        "mma.sync.aligned.m16n8k8.row.col.f32.tf32.tf32.f32 "
        "{%0,%1,%2,%3}, {%4,%5,%6,%7}, {%8,%9}, {%0,%1,%2,%3};"
        : "+f"(c[0]), "+f"(c[1]), "+f"(c[2]), "+f"(c[3])
        : "r"(a0), "r"(a1), "r"(a2), "r"(a3), "r"(b0), "r"(b1));
}
__device__ __forceinline__ void cp16(uint32_t s, const void* g, bool pr) {
    int b = pr ? 16 : 0;
    asm volatile("cp.async.cg.shared.global [%0], [%1], 16, %2;" :: "r"(s), "l"(g), "r"(b));
}

__global__ void k_zero() { if (threadIdx.x < EE) g_cnt[threadIdx.x] = 0; }

// ---- router gate + token rms ----
__global__ void __launch_bounds__(256) k_gate(const float* __restrict__ stream,
                                              const float* __restrict__ router_w,
                                              float* __restrict__ out_gate)
{
    int token = blockIdx.x, b = token / TT, t = token % TT, tid = threadIdx.x;
    __shared__ float route[DD], red[256], logit[EE];
    const float* sp0 = stream + ((size_t)b * NS * TT + t) * DD;
    float ss = 0.f;
    for (int dd = tid; dd < DD; dd += 256) {
        float v0 = sp0[dd], v1 = sp0[(size_t)TT*DD + dd];
        float v2 = sp0[2*(size_t)TT*DD + dd], v3 = sp0[3*(size_t)TT*DD + dd];
        ss += v0*v0 + v1*v1 + v2*v2 + v3*v3;
        route[dd] = 0.25f * (v0 + v1 + v2 + v3);
    }
    red[tid] = ss; __syncthreads();
    for (int s = 128; s > 0; s >>= 1) { if (tid < s) red[tid] += red[tid+s]; __syncthreads(); }
    if (tid == 0) g_srms[token] = rsqrtf(red[0] / (float)NDIM + EPS_F);
    int warp = tid >> 5, lane = tid & 31;
    for (int e = warp; e < EE; e += 8) {
        const float* rw = router_w + (size_t)e * DD;
        float acc = 0.f;
        for (int dd = lane; dd < DD; dd += 32) acc += route[dd] * rw[dd];
        #pragma unroll
        for (int o = 16; o > 0; o >>= 1) acc += __shfl_down_sync(0xffffffffu, acc, o);
        if (lane == 0) logit[e] = acc;
    }
    __syncthreads();
    if (tid == 0) {
        float p[EE], mx = -1e30f;
        #pragma unroll
        for (int e = 0; e < EE; e++) mx = fmaxf(mx, logit[e]);
        float sum = 0.f;
        #pragma unroll
        for (int e = 0; e < EE; e++) { p[e] = expf(logit[e] - mx); sum += p[e]; }
        float inv = 1.f / sum;
        #pragma unroll
        for (int e = 0; e < EE; e++) p[e] *= inv;
        int ord[EE];
        #pragma unroll
        for (int e = 0; e < EE; e++) ord[e] = e;
        for (int i = 1; i < EE; i++) {
            int oi = ord[i]; float pi = p[oi]; int j = i - 1;
            while (j >= 0 && p[ord[j]] < pi) { ord[j+1] = ord[j]; j--; }
            ord[j+1] = oi;
        }
        float cum = 0.f, gate[EE];
        #pragma unroll
        for (int e = 0; e < EE; e++) gate[e] = 0.f;
        for (int r = 0; r < EE; r++) {
            int e = ord[r];
            if ((r == 0) || (cum < 0.8f && r < 4)) gate[e] = p[e];
            cum += p[e];
        }
        for (int e = 0; e < EE; e++) {
            float g = gate[e];
            out_gate[(size_t)token*EE + e] = g;
            g_gatev[token*EE + e] = g;
            int row = -1;
            if (g > 0.f) { row = atomicAdd(&g_cnt[e], 1); g_tok[e*CAP + row] = token; }
            g_row[token*EE + e] = row;
        }
    }
}

// ---- base: vectorized, tf32-rounded + k-interleaved ----
__global__ void __launch_bounds__(256) k_base(const float* __restrict__ stream)
{
    int token = blockIdx.x, b = token / TT, t = token % TT;
    float s = g_srms[token];
    const float* sp0 = stream + ((size_t)b * NS * TT + t) * DD;
    float* dst = g_base + (size_t)token * NDIM;
    #pragma unroll
    for (int u = 0; u < 2; u++) {
        int g = threadIdx.x + u * 256;
        int j0 = g * 8, i = j0 >> 10, dd0 = j0 & 1023;
        const float* p = sp0 + (size_t)i * TT * DD + dd0;
        float4 lo = *(const float4*)p, hi = *(const float4*)(p + 4);
        float sv[8] = {lo.x*s, lo.y*s, lo.z*s, lo.w*s, hi.x*s, hi.y*s, hi.z*s, hi.w*s};
        float4 o0, o1; perm8(sv, o0, o1);
        *(float4*)(dst + j0) = o0; *(float4*)(dst + j0 + 4) = o1;
    }
}

// ---- phi weights pack (fold mhc norm), vectorized ----
__global__ void __launch_bounds__(256) k_pack(const float* __restrict__ mhc_norm_w,
                                              const float* __restrict__ pw,
                                              const float* __restrict__ ow,
                                              const float* __restrict__ rw)
{
    int g = blockIdx.x * 256 + threadIdx.x;
    int e = g / 12288;
    int rem = g - e * 12288;
    int r = rem >> 9;
    int j0 = (rem & 511) * 8;
    const float* wsrc;
    if (r < 4)      wsrc = pw + ((size_t)e*4 + r)*NDIM + j0;
    else if (r < 8) wsrc = ow + ((size_t)e*4 + (r-4))*NDIM + j0;
    else            wsrc = rw + ((size_t)e*16 + (r-8))*NDIM + j0;
    const float* nsrc = mhc_norm_w + (size_t)e*NDIM + j0;
    float4 w0 = *(const float4*)wsrc, w1 = *(const float4*)(wsrc + 4);
    float4 n0 = *(const float4*)nsrc, n1 = *(const float4*)(nsrc + 4);
    float sv[8] = {w0.x*n0.x, w0.y*n0.y, w0.z*n0.z, w0.w*n0.w,
                   w1.x*n1.x, w1.y*n1.y, w1.z*n1.z, w1.w*n1.w};
    float4 o0, o1; perm8(sv, o0, o1);
    float* q = g_phiW + (size_t)g * 8;
    *(float4*)q = o0; *(float4*)(q + 4) = o1;
}

// ---- weight pack: compile-time strides, vectorized, grid-stride ----
template <int KACT, int KPAD>
__global__ void __launch_bounds__(256) k_packw8(const float* __restrict__ src,
                                                float* __restrict__ dst, long ngroups)
{
    constexpr int GPR = KPAD / 8;
    long g0 = (long)blockIdx.x * 256 + threadIdx.x;
    long stride = (long)gridDim.x * 256;
    for (long g = g0; g < ngroups; g += stride) {
        long row = g / GPR;
        int gi = (int)(g - row * GPR);
        float4 o0, o1;
        if (gi * 8 + 8 <= KACT) {
            const float* p = src + row * KACT + gi * 8;
            float4 lo = *(const float4*)p, hi = *(const float4*)(p + 4);
            float sv[8] = {lo.x, lo.y, lo.z, lo.w, hi.x, hi.y, hi.z, hi.w};
            perm8(sv, o0, o1);
        } else {
            o0 = make_float4(0.f, 0.f, 0.f, 0.f); o1 = o0;
        }
        float* q = dst + g * 8;
        *(float4*)q = o0; *(float4*)(q + 4) = o1;
    }
}

// ---- tf32 GEMM (R9, unchanged) ----
template <int MODE>
__global__ void __launch_bounds__(256, 2) k_gemm(
    const float* __restrict__ A, int lda,
    const float* __restrict__ W, int ldw, int Ntot, int KT,
    float* __restrict__ Cf, float* __restrict__ Ci, int ldc,
    const float* __restrict__ Aux, int ldaux, int cntOv)
{
    extern __shared__ float sm[];
    int e = blockIdx.z;
    int cnt = (cntOv >= 0) ? cntOv : g_cnt[e];
    int m0 = blockIdx.x * 128;
    if (m0 >= cnt) return;
    int n0 = blockIdx.y * 128;

    A += (size_t)e * CAP * lda;
    W += (size_t)e * Ntot * ldw;
    size_t co = (size_t)e * CAP * ldc;
    if (Cf) Cf += co;
    if (Ci) Ci += co;
    if (Aux) Aux += (size_t)e * CAP * ldaux;

    uint32_t sb = (uint32_t)__cvta_generic_to_shared(sm);
    int tid = threadIdx.x, warp = tid >> 5, lane = tid & 31;
    int wm = warp >> 1, wn = warp & 1;
    int qr = lane >> 2, qc = lane & 3;

    float acc[2][8][4];
    #pragma unroll
    for (int mt = 0; mt < 2; mt++)
        #pragma unroll
        for (int nt = 0; nt < 8; nt++)
            #pragma unroll
            for (int q = 0; q < 4; q++) acc[mt][nt][q] = 0.f;

    auto load_stage = [&](int kt, int stg) {
        int k0 = kt * 32;
        #pragma unroll
        for (int s4 = 0; s4 < 4; s4++) {
            int f = tid + s4*256, r = f >> 3, c = f & 7;
            cp16(sb + ((stg*STGF + r*RS + c*4) << 2), A + (size_t)(m0 + r)*lda + k0 + c*4, true);
        }
        #pragma unroll
        for (int s4 = 0; s4 < 4; s4++) {
            int f = tid + s4*256, r = f >> 3, c = f & 7;
            bool pr = (n0 + r) < Ntot;
            const float* gp = W + (size_t)(n0 + r)*ldw + k0 + c*4;
            cp16(sb + ((stg*STGF + 128*RS + r*RS + c*4) << 2), pr ? gp : W, pr);
        }
        asm volatile("cp.async.commit_group;");
    };

    load_stage(0, 0);

    for (int kt = 0; kt < KT; kt++) {
        if (kt + 1 < KT) load_stage(kt + 1, (kt + 1) & 1);
        if (kt + 1 < KT) asm volatile("cp.async.wait_group 1;");
        else             asm volatile("cp.async.wait_group 0;");
        __syncthreads();

        int stg = kt & 1;
        const float* Asm = sm + stg * STGF;
        const float* Bsm = Asm + 128 * RS;

        #pragma unroll
        for (int ks = 0; ks < 4; ks++) {
            int kb = ks * 8 + qc * 2;
            const float* ap = Asm + (wm*32 + qr)*RS + kb;
            float2 a0 = *(const float2*)ap;
            float2 a1 = *(const float2*)(ap + 8*RS);
            float2 a2 = *(const float2*)(ap + 16*RS);
            float2 a3 = *(const float2*)(ap + 24*RS);
            const float* bp = Bsm + (wn*64 + qr)*RS + kb;
            #pragma unroll
            for (int nt = 0; nt < 8; nt++) {
                float2 bb = *(const float2*)(bp + nt*8*RS);
                uint32_t b0 = __float_as_uint(bb.x), b1 = __float_as_uint(bb.y);
                mma8(acc[0][nt], __float_as_uint(a0.x), __float_as_uint(a1.x),
                     __float_as_uint(a0.y), __float_as_uint(a1.y), b0, b1);
                mma8(acc[1][nt], __float_as_uint(a2.x), __float_as_uint(a3.x),
                     __float_as_uint(a2.y), __float_as_uint(a3.y), b0, b1);
            }
        }
        __syncthreads();
    }

    #pragma unroll
    for (int mt = 0; mt < 2; mt++) {
        #pragma unroll
        for (int nt = 0; nt < 8; nt++) {
            int n = n0 + wn*64 + nt*8 + qc*2;
            #pragma unroll
            for (int half = 0; half < 2; half++) {
                int m = m0 + wm*32 + mt*16 + qr + half*8;
                if (m >= cnt) continue;
                float v0 = acc[mt][nt][half*2], v1 = acc[mt][nt][half*2 + 1];
                size_t off = (size_t)m * ldc + n;
                if (MODE == 0) {
                    if (n < Ntot) { float2 s2 = {v0, v1}; *(float2*)(Cf + off) = s2; }
                } else if (MODE == 2) {
                    if (n < Ntot) {
                        float2 s2 = {1.f/(1.f+expf(-v0)), 1.f/(1.f+expf(-v1))};
                        *(float2*)(Cf + off) = s2;
                    }
                } else if (MODE == 5) {
                    if (n < Ntot) {
                        float2 s2 = {v0 * Aux[(size_t)m*ldaux + n], v1 * Aux[(size_t)m*ldaux + n + 1]};
                        *(float2*)(Cf + off) = s2;
                    }
                } else {  // MODE 1: silu -> interleaved tf32
                    size_t rowo = (size_t)m * ldc + (n & ~7);
                    int p0 = posk(n & 7), p1 = posk((n + 1) & 7);
                    if (n < Ntot) {
                        float x0 = v0/(1.f+expf(-v0)), x1 = v1/(1.f+expf(-v1));
                        Ci[rowo + p0] = f2tf_f(x0);
                        Ci[rowo + p1] = f2tf_f(x1);
                    }
                }
            }
        }
    }
}

// ---- fused gate/up GEMM: P2 = silu(A@Wg^T) * (A@Wu^T), interleaved tf32 ----
__global__ void __launch_bounds__(512, 1) k_gemmF(
    const float* __restrict__ A,
    const float* __restrict__ Wg, const float* __restrict__ Wu,
    float* __restrict__ Ci)
{
    extern __shared__ float sm[];
    int e = blockIdx.z;
    int cnt = g_cnt[e];
    int m0 = blockIdx.x * 128;
    if (m0 >= cnt) return;
    int n0 = blockIdx.y * 128;

    A  += (size_t)e * CAP * DD;
    Wg += (size_t)e * DFFN * DD;
    Wu += (size_t)e * DFFN * DD;
    Ci += (size_t)e * CAP * LDP;

    uint32_t sb = (uint32_t)__cvta_generic_to_shared(sm);
    int tid = threadIdx.x, warp = tid >> 5, lane = tid & 31;
    int wm = warp >> 3, wn = warp & 7;       // 2m x 8n warps; warp tile 64m x 16n (x2 outputs)
    int qr = lane >> 2, qc = lane & 3;

    float accG[4][2][4], accU[4][2][4];
    #pragma unroll
    for (int mt = 0; mt < 4; mt++)
        #pragma unroll
        for (int nt = 0; nt < 2; nt++)
            #pragma unroll
            for (int q = 0; q < 4; q++) { accG[mt][nt][q] = 0.f; accU[mt][nt][q] = 0.f; }

    auto load_stage = [&](int kt, int stg) {
        int k0 = kt * 32;
        #pragma unroll
        for (int i = 0; i < 6; i++) {
            int f = tid + i*512, r = f >> 3, c = f & 7;
            const float* gp; bool pr = true;
            if (r < 128) {
                gp = A + (size_t)(m0 + r)*DD + k0 + c*4;
            } else if (r < 256) {
                int nr = n0 + r - 128; pr = nr < DFFN;
                gp = pr ? (Wg + (size_t)nr*DD + k0 + c*4) : A;
            } else {
                int nr = n0 + r - 256; pr = nr < DFFN;
                gp = pr ? (Wu + (size_t)nr*DD + k0 + c*4) : A;
            }
            cp16(sb + ((stg*STGFF + r*RS + c*4) << 2), gp, pr);
        }
        asm volatile("cp.async.commit_group;");
    };

    const int KT = DD / 32;
    load_stage(0, 0);

    for (int kt = 0; kt < KT; kt++) {
        if (kt + 1 < KT) load_stage(kt + 1, (kt + 1) & 1);
        if (kt + 1 < KT) asm volatile("cp.async.wait_group 1;");
        else             asm volatile("cp.async.wait_group 0;");
        __syncthreads();

        int stg = kt & 1;
        const float* Asm = sm + stg * STGFF;

        #pragma unroll
        for (int ks = 0; ks < 4; ks++) {
            int kb = ks * 8 + qc * 2;
            float2 al[4], ah[4];
            #pragma unroll
            for (int mt = 0; mt < 4; mt++) {
                const float* ap = Asm + (wm*64 + mt*16 + qr)*RS + kb;
                al[mt] = *(const float2*)ap;
                ah[mt] = *(const float2*)(ap + 8*RS);
            }
            #pragma unroll
            for (int nt = 0; nt < 2; nt++) {
                int br = (wn*16 + nt*8 + qr)*RS + kb;
                float2 bg = *(const float2*)(Asm + 128*RS + br);
                float2 bu = *(const float2*)(Asm + 256*RS + br);
                uint32_t bg0 = __float_as_uint(bg.x), bg1 = __float_as_uint(bg.y);
                uint32_t bu0 = __float_as_uint(bu.x), bu1 = __float_as_uint(bu.y);
                #pragma unroll
                for (int mt = 0; mt < 4; mt++) {
                    uint32_t a0 = __float_as_uint(al[mt].x), a1 = __float_as_uint(ah[mt].x);
                    uint32_t a2 = __float_as_uint(al[mt].y), a3 = __float_as_uint(ah[mt].y);
                    mma8(accG[mt][nt], a0, a1, a2, a3, bg0, bg1);
                    mma8(accU[mt][nt], a0, a1, a2, a3, bu0, bu1);
                }
            }
        }
        __syncthreads();
    }

    #pragma unroll
    for (int mt = 0; mt < 4; mt++) {
        #pragma unroll
        for (int nt = 0; nt < 2; nt++) {
            int n = n0 + wn*16 + nt*8 + qc*2;
            #pragma unroll
            for (int half = 0; half < 2; half++) {
                int m = m0 + wm*64 + mt*16 + qr + half*8;
                if (m >= cnt) continue;
                size_t rowo = (size_t)m * LDP + (n & ~7);
                int p0 = posk(n & 7), p1 = posk((n + 1) & 7);
                if (n < DFFN) {
                    float gv0 = accG[mt][nt][half*2], gv1 = accG[mt][nt][half*2 + 1];
                    float uv0 = accU[mt][nt][half*2], uv1 = accU[mt][nt][half*2 + 1];
                    float x0 = (gv0/(1.f+expf(-gv0))) * uv0;
                    float x1 = (gv1/(1.f+expf(-gv1))) * uv1;
                    Ci[rowo + p0] = f2tf_f(x0);
                    Ci[rowo + p1] = f2tf_f(x1);
                } else if (n < LDP) {
                    Ci[rowo + p0] = 0.f;
                    Ci[rowo + p1] = 0.f;
                }
            }
        }
    }
}

// ---- per active pair: gates, sinkhorn, h, hn ----
__global__ void __launch_bounds__(128) k_hn(const float* __restrict__ stream,
                                            const float* __restrict__ b_pre,
                                            const float* __restrict__ b_post,
                                            const float* __restrict__ b_res,
                                            const float* __restrict__ alpha_pre,
                                            const float* __restrict__ alpha_post,
                                            const float* __restrict__ alpha_res,
                                            const float* __restrict__ sw_norm_w)
{
    int row = blockIdx.x, e = blockIdx.y;
    if (row >= g_cnt[e]) return;
    int token = g_tok[e*CAP + row], b = token / TT, t = token % TT, tid = threadIdx.x;
    __shared__ float hpre[NS], red2[4];

    if (tid == 0) {
        const float* d = g_dots + (size_t)token*384 + e*24;
        size_t slot = (size_t)e*CAP + row;
        float ap = alpha_pre[e], ao = alpha_post[e], ar = alpha_res[e];
        #pragma unroll
        for (int i = 0; i < NS; i++)
            hpre[i] = 1.f / (1.f + expf(-(ap*d[i] + b_pre[e*NS+i])));
        #pragma unroll
        for (int i = 0; i < NS; i++)
            g_Hpost[slot*NS+i] = 2.f / (1.f + expf(-(ao*d[4+i] + b_post[e*NS+i])));
        float M[16];
        #pragma unroll
        for (int k = 0; k < 16; k++) M[k] = expf(ar*d[8+k] + b_res[e*16+k]);
        for (int it = 0; it < 6; it++) {
            #pragma unroll
            for (int i = 0; i < 4; i++) {
                float ir = 1.f / (M[i*4]+M[i*4+1]+M[i*4+2]+M[i*4+3]);
                M[i*4]*=ir; M[i*4+1]*=ir; M[i*4+2]*=ir; M[i*4+3]*=ir;
            }
            #pragma unroll
            for (int j = 0; j < 4; j++) {
                float ic = 1.f / (M[j]+M[4+j]+M[8+j]+M[12+j]);
                M[j]*=ic; M[4+j]*=ic; M[8+j]*=ic; M[12+j]*=ic;
            }
        }
        #pragma unroll
        for (int k = 0; k < 16; k++) g_Hres[slot*16+k] = M[k];
    }
    __syncthreads();

    const float* sp0 = stream + ((size_t)b*NS*TT + t) * DD;
    float h0 = hpre[0], h1 = hpre[1], h2 = hpre[2], h3 = hpre[3];
    float hreg[8], hq = 0.f;
    #pragma unroll
    for (int u = 0; u < 8; u++) {
        int dd = tid + u*128;
        float h = h0*sp0[dd] + h1*sp0[(size_t)TT*DD+dd]
                + h2*sp0[2*(size_t)TT*DD+dd] + h3*sp0[3*(size_t)TT*DD+dd];
        hreg[u] = h; hq += h*h;
    }
    int lane = tid & 31, warp = tid >> 5;
    #pragma unroll
    for (int o = 16; o > 0; o >>= 1) hq += __shfl_down_sync(0xffffffffu, hq, o);
    if (lane == 0) red2[warp] = hq;
    __syncthreads();
    if (tid == 0) red2[0] = rsqrtf((red2[0]+red2[1]+red2[2]+red2[3]) / (float)DD + EPS_F);
    __syncthreads();
    float sh = red2[0];
    const float* snw = sw_norm_w + (size_t)e*DD;
    float* hn = g_HN + ((size_t)e*CAP + row) * DD;
    #pragma unroll
    for (int u = 0; u < 8; u++) {
        int dd = tid + u*128;
        float v = hreg[u] * sh * snw[dd];
        hn[(dd & ~7) | posk(dd & 7)] = f2tf_f(v);
    }
}

// ---- combine res + post ----
__global__ void __launch_bounds__(128) k_out(const float* __restrict__ stream,
                                             float* __restrict__ outp)
{
    int token = blockIdx.x, b = token / TT, t = token % TT, tid = threadIdx.x;
    const float* sp0 = stream + ((size_t)b*NS*TT + t) * DD;
    float st[4][8], acc[4][8];
    #pragma unroll
    for (int i = 0; i < 4; i++)
        #pragma unroll
        for (int j = 0; j < 8; j++) {
            st[i][j] = sp0[(size_t)i*TT*DD + tid + j*128];
            acc[i][j] = 0.f;
        }
    for (int e = 0; e < EE; e++) {
        int row = g_row[token*EE + e];
        if (row < 0) continue;
        float g = g_gatev[token*EE + e];
        size_t slot = (size_t)e*CAP + row;
        float Hr[16], Hp[4];
        #pragma unroll
        for (int k = 0; k < 16; k++) Hr[k] = g_Hres[slot*16+k];
        #pragma unroll
        for (int i = 0; i < 4; i++) Hp[i] = g_Hpost[slot*4+i];
        const float* o = g_OUT + slot*DD;
        #pragma unroll
        for (int j = 0; j < 8; j++) {
            float ov = o[tid + j*128];
            #pragma unroll
            for (int i = 0; i < 4; i++) {
                float r = Hr[i*4]*st[0][j] + Hr[i*4+1]*st[1][j]
                        + Hr[i*4+2]*st[2][j] + Hr[i*4+3]*st[3][j];
                acc[i][j] += g * (r + Hp[i]*ov);
            }
        }
    }
    #pragma unroll
    for (int i = 0; i < 4; i++)
        #pragma unroll
        for (int j = 0; j < 8; j++)
            outp[((size_t)(b*NS+i)*TT + t)*DD + tid + j*128] = acc[i][j];
}

#define GSA(p, s) cudaGetSymbolAddress((void**)&p, s)

extern "C" void kernel_launch(void* const* d_in, const int* in_sizes, int n_in,
                              void* d_out, int out_size)
{
    (void)in_sizes; (void)n_in; (void)out_size;
    const float* stream   = (const float*)d_in[0];
    const float* router_w = (const float*)d_in[1];
    const float* mhc      = (const float*)d_in[2];
    const float* phi_pre  = (const float*)d_in[3];
    const float* phi_post = (const float*)d_in[4];
    const float* phi_res  = (const float*)d_in[5];
    const float* b_pre    = (const float*)d_in[6];
    const float* b_post   = (const float*)d_in[7];
    const float* b_res    = (const float*)d_in[8];
    const float* a_pre    = (const float*)d_in[9];
    const float* a_post   = (const float*)d_in[10];
    const float* a_res    = (const float*)d_in[11];
    const float* sw_nw    = (const float*)d_in[12];
    const float* wd_w     = (const float*)d_in[13];
    const float* wu_w     = (const float*)d_in[14];
    const float* gate_w   = (const float*)d_in[15];
    const float* up_w     = (const float*)d_in[16];
    const float* down_w   = (const float*)d_in[17];

    float* outp = (float*)d_out;
    float* out_gate = outp + (size_t)BB*NS*TT*DD;

    cudaFuncSetAttribute(k_gemm<0>, cudaFuncAttributeMaxDynamicSharedMemorySize, SMEM_DYN);
    cudaFuncSetAttribute(k_gemm<1>, cudaFuncAttributeMaxDynamicSharedMemorySize, SMEM_DYN);
    cudaFuncSetAttribute(k_gemm<2>, cudaFuncAttributeMaxDynamicSharedMemorySize, SMEM_DYN);
    cudaFuncSetAttribute(k_gemm<5>, cudaFuncAttributeMaxDynamicSharedMemorySize, SMEM_DYN);
    cudaFuncSetAttribute(k_gemmF, cudaFuncAttributeMaxDynamicSharedMemorySize, SMEM_F);

    float *base, *HN, *T1, *GS, *P2, *OUT, *dots, *phiW, *wd, *wu, *gt, *up, *dn;
    GSA(base, g_base); GSA(HN, g_HN); GSA(T1, g_T1); GSA(GS, g_GS);
    GSA(P2, g_P2); GSA(OUT, g_OUT); GSA(dots, g_dots);
    GSA(phiW, g_phiW); GSA(wd, g_wd); GSA(wu, g_wu); GSA(gt, g_gt);
    GSA(up, g_up); GSA(dn, g_dn);

    k_zero<<<1, 32>>>();
    k_gate<<<BT, 256>>>(stream, router_w, out_gate);
    k_base<<<BT, 256>>>(stream);
    k_pack<<<(EE*24*NDIM/8)/256, 256>>>(mhc, phi_pre, phi_post, phi_res);
    {
        long n1 = (long)EE*DD*DD/8;
        long n2 = (long)EE*DFFN*DD/8;
        long n3 = (long)EE*DD*LDP/8;
        unsigned b1 = (unsigned)((n1 + 1023) / 1024);
        unsigned b2 = (unsigned)((n2 + 1023) / 1024);
        unsigned b3 = (unsigned)((n3 + 1023) / 1024);
        k_packw8<DD, DD><<<b1, 256>>>(wd_w, wd, n1);
        k_packw8<DD, DD><<<b1, 256>>>(wu_w, wu, n1);
        k_packw8<DD, DD><<<b2, 256>>>(gate_w, gt, n2);
        k_packw8<DD, DD><<<b2, 256>>>(up_w, up, n2);
        k_packw8<DFFN, LDP><<<b3, 256>>>(down_w, dn, n3);
    }

    // dots = base @ phiW^T  (N=384, K=4096)
    k_gemm<0><<<dim3(32,3,1), 256, SMEM_DYN>>>(base, NDIM, phiW, NDIM, 384, NDIM/32,
                                               dots, (float*)0, 384, (const float*)0, 0, BT);

    k_hn<<<dim3(CAP, EE), 128>>>(stream, b_pre, b_post, b_res, a_pre, a_post, a_res, sw_nw);

    dim3 gD(32, 8, EE);

    // T1 = silu(HN @ wd^T) -> interleaved tf32
    k_gemm<1><<<gD, 256, SMEM_DYN>>>(HN, DD, wd, DD, DD, DD/32,
                                     (float*)0, T1, DD, (const float*)0, 0, -1);
    // GS = sigmoid(T1 @ wu^T) -> f32
    k_gemm<2><<<gD, 256, SMEM_DYN>>>(T1, DD, wu, DD, DD, DD/32,
                                     GS, (float*)0, DD, (const float*)0, 0, -1);
    // P2 = silu(HN @ gt^T) * (HN @ up^T) -> interleaved tf32 (fused, pad to LDP)
    k_gemmF<<<dim3(32,13,EE), 512, SMEM_F>>>(HN, gt, up, P2);
    // OUT = (P2 @ dn^T) * GS -> f32
    k_gemm<5><<<gD, 256, SMEM_DYN>>>(P2, LDP, dn, LDP, DD, LDP/32,
                                     OUT, (float*)0, DD, GS, DD, -1);

    k_out<<<BT, 128>>>(stream, outp);
}

// round 11
// speedup vs baseline: 2.5042x; 1.6949x over previous
#include <cuda_runtime.h>
#include <cuda_fp16.h>
#include <math.h>
#include <stdint.h>

#define BB 2
#define NS 4
#define TT 2048
#define DD 1024
#define EE 16
#define NDIM 4096
#define DFFN 1656
#define LDP 1664
#define BT (BB*TT)
#define CAP BT
#define EPS_F 1.1920929e-7f
#define RSH 80                   // smem row stride in halves (160B: conflict-free LDS.64)
#define KC 64                    // k per chunk (halves)
#define STG_B 40960              // bytes/stage: 2 blocks x 128 rows x 160B
#define SMEM_DYN (2*STG_B)
#define STG_BF 61440             // 3 blocks
#define SMEM_F (2*STG_BF)

typedef __half hf;

// ---- device scratch ----
__device__ __align__(16) hf g_base[(size_t)BT*NDIM];
__device__ __align__(16) hf g_HN [(size_t)EE*CAP*DD];
__device__ __align__(16) hf g_T1 [(size_t)EE*CAP*DD];
__device__ __align__(16) hf g_P2 [(size_t)EE*CAP*LDP];
__device__ __align__(16) hf g_phiW[(size_t)EE*24*NDIM];
__device__ __align__(16) hf g_wd[(size_t)EE*DD*DD];
__device__ __align__(16) hf g_wu[(size_t)EE*DD*DD];
__device__ __align__(16) hf g_gt[(size_t)EE*DFFN*DD];
__device__ __align__(16) hf g_up[(size_t)EE*DFFN*DD];
__device__ __align__(16) hf g_dn[(size_t)EE*DD*LDP];
__device__ __align__(16) float g_GS [(size_t)EE*CAP*DD];
__device__ __align__(16) float g_OUT[(size_t)EE*CAP*DD];
__device__ __align__(16) float g_dots[(size_t)BT*384];
__device__ float g_srms[BT];
__device__ int   g_row[BT*EE];
__device__ float g_gatev[BT*EE];
__device__ int   g_tok[EE*CAP];
__device__ int   g_cnt[EE];
__device__ float g_Hpost[(size_t)EE*CAP*NS];
__device__ float g_Hres[(size_t)EE*CAP*16];

// ---- helpers ----
// fragment interleave within 16-group: pos(k) = ((k>>1)&3)*4 + ((k>>3)&1)*2 + (k&1)
// inverse: k(p) = ((p>>1)&1)*8 + (p>>2)*2 + (p&1)
__device__ __forceinline__ int posh(int n) {
    return ((n >> 1) & 3) * 4 + ((n >> 3) & 1) * 2 + (n & 1);
}
// perm16: src 16 floats -> 8 half2 in interleaved order (pairs 01,89,23,AB,45,CD,67,EF)
__device__ __forceinline__ void perm16(const float* s, __half2* o) {
    const int pr[8] = {0, 8, 2, 10, 4, 12, 6, 14};
    #pragma unroll
    for (int j = 0; j < 8; j++)
        o[j] = __floats2half2_rn(s[pr[j]], s[pr[j] + 1]);
}
__device__ __forceinline__ void mma16(float* c, uint32_t a0, uint32_t a1, uint32_t a2,
                                      uint32_t a3, uint32_t b0, uint32_t b1) {
    asm volatile(
        "mma.sync.aligned.m16n8k16.row.col.f32.f16.f16.f32 "
        "{%0,%1,%2,%3}, {%4,%5,%6,%7}, {%8,%9}, {%0,%1,%2,%3};"
        : "+f"(c[0]), "+f"(c[1]), "+f"(c[2]), "+f"(c[3])
        : "r"(a0), "r"(a1), "r"(a2), "r"(a3), "r"(b0), "r"(b1));
}
__device__ __forceinline__ void cp16(uint32_t s, const void* g, bool pr) {
    int b = pr ? 16 : 0;
    asm volatile("cp.async.cg.shared.global [%0], [%1], 16, %2;" :: "r"(s), "l"(g), "r"(b));
}

__global__ void k_zero() { if (threadIdx.x < EE) g_cnt[threadIdx.x] = 0; }

// ---- router gate + token rms ----
__global__ void __launch_bounds__(256) k_gate(const float* __restrict__ stream,
                                              const float* __restrict__ router_w,
                                              float* __restrict__ out_gate)
{
    int token = blockIdx.x, b = token / TT, t = token % TT, tid = threadIdx.x;
    __shared__ float route[DD], red[256], logit[EE];
    const float* sp0 = stream + ((size_t)b * NS * TT + t) * DD;
    float ss = 0.f;
    for (int dd = tid; dd < DD; dd += 256) {
        float v0 = sp0[dd], v1 = sp0[(size_t)TT*DD + dd];
        float v2 = sp0[2*(size_t)TT*DD + dd], v3 = sp0[3*(size_t)TT*DD + dd];
        ss += v0*v0 + v1*v1 + v2*v2 + v3*v3;
        route[dd] = 0.25f * (v0 + v1 + v2 + v3);
    }
    red[tid] = ss; __syncthreads();
    for (int s = 128; s > 0; s >>= 1) { if (tid < s) red[tid] += red[tid+s]; __syncthreads(); }
    if (tid == 0) g_srms[token] = rsqrtf(red[0] / (float)NDIM + EPS_F);
    int warp = tid >> 5, lane = tid & 31;
    for (int e = warp; e < EE; e += 8) {
        const float* rw = router_w + (size_t)e * DD;
        float acc = 0.f;
        for (int dd = lane; dd < DD; dd += 32) acc += route[dd] * rw[dd];
        #pragma unroll
        for (int o = 16; o > 0; o >>= 1) acc += __shfl_down_sync(0xffffffffu, acc, o);
        if (lane == 0) logit[e] = acc;
    }
    __syncthreads();
    if (tid == 0) {
        float p[EE], mx = -1e30f;
        #pragma unroll
        for (int e = 0; e < EE; e++) mx = fmaxf(mx, logit[e]);
        float sum = 0.f;
        #pragma unroll
        for (int e = 0; e < EE; e++) { p[e] = expf(logit[e] - mx); sum += p[e]; }
        float inv = 1.f / sum;
        #pragma unroll
        for (int e = 0; e < EE; e++) p[e] *= inv;
        int ord[EE];
        #pragma unroll
        for (int e = 0; e < EE; e++) ord[e] = e;
        for (int i = 1; i < EE; i++) {
            int oi = ord[i]; float pi = p[oi]; int j = i - 1;
            while (j >= 0 && p[ord[j]] < pi) { ord[j+1] = ord[j]; j--; }
            ord[j+1] = oi;
        }
        float cum = 0.f, gate[EE];
        #pragma unroll
        for (int e = 0; e < EE; e++) gate[e] = 0.f;
        for (int r = 0; r < EE; r++) {
            int e = ord[r];
            if ((r == 0) || (cum < 0.8f && r < 4)) gate[e] = p[e];
            cum += p[e];
        }
        for (int e = 0; e < EE; e++) {
            float g = gate[e];
            out_gate[(size_t)token*EE + e] = g;
            g_gatev[token*EE + e] = g;
            int row = -1;
            if (g > 0.f) { row = atomicAdd(&g_cnt[e], 1); g_tok[e*CAP + row] = token; }
            g_row[token*EE + e] = row;
        }
    }
}

// ---- base: half, interleaved (one 16-group per thread) ----
__global__ void __launch_bounds__(256) k_base(const float* __restrict__ stream)
{
    int token = blockIdx.x, b = token / TT, t = token % TT;
    float s = g_srms[token];
    const float* sp0 = stream + ((size_t)b * NS * TT + t) * DD;
    hf* dst = g_base + (size_t)token * NDIM;
    int j0 = threadIdx.x * 16;                 // 256 groups of 16
    int i = j0 >> 10, dd0 = j0 & 1023;
    const float* p = sp0 + (size_t)i * TT * DD + dd0;
    float sv[16];
    #pragma unroll
    for (int q = 0; q < 4; q++) {
        float4 v = *(const float4*)(p + q*4);
        sv[q*4+0] = v.x*s; sv[q*4+1] = v.y*s; sv[q*4+2] = v.z*s; sv[q*4+3] = v.w*s;
    }
    __half2 o[8]; perm16(sv, o);
    *(uint4*)(dst + j0) = *(uint4*)o;
    *(uint4*)(dst + j0 + 8) = *(uint4*)(o + 4);
}

// ---- phi weights pack (fold mhc norm) ----
__global__ void __launch_bounds__(256) k_pack(const float* __restrict__ mhc_norm_w,
                                              const float* __restrict__ pw,
                                              const float* __restrict__ ow,
                                              const float* __restrict__ rw)
{
    int g = blockIdx.x * 256 + threadIdx.x;    // EE*24*NDIM/16 = 98304 groups
    int e = g / 6144;                          // 24*NDIM/16 per expert
    int rem = g - e * 6144;
    int r = rem >> 8;                          // NDIM/16 = 256 groups per row
    int j0 = (rem & 255) * 16;
    const float* wsrc;
    if (r < 4)      wsrc = pw + ((size_t)e*4 + r)*NDIM + j0;
    else if (r < 8) wsrc = ow + ((size_t)e*4 + (r-4))*NDIM + j0;
    else            wsrc = rw + ((size_t)e*16 + (r-8))*NDIM + j0;
    const float* nsrc = mhc_norm_w + (size_t)e*NDIM + j0;
    float sv[16];
    #pragma unroll
    for (int q = 0; q < 4; q++) {
        float4 w = *(const float4*)(wsrc + q*4);
        float4 n = *(const float4*)(nsrc + q*4);
        sv[q*4+0] = w.x*n.x; sv[q*4+1] = w.y*n.y; sv[q*4+2] = w.z*n.z; sv[q*4+3] = w.w*n.w;
    }
    __half2 o[8]; perm16(sv, o);
    hf* q = g_phiW + (size_t)g * 16;
    *(uint4*)q = *(uint4*)o;
    *(uint4*)(q + 8) = *(uint4*)(o + 4);
}

// ---- weight pack fp32 -> half interleaved, K pad ----
template <int KACT, int KPAD>
__global__ void __launch_bounds__(256) k_packw16(const float* __restrict__ src,
                                                 hf* __restrict__ dst, long ngroups)
{
    constexpr int GPR = KPAD / 16;
    long g0 = (long)blockIdx.x * 256 + threadIdx.x;
    long stride = (long)gridDim.x * 256;
    for (long g = g0; g < ngroups; g += stride) {
        long row = g / GPR;
        int gi = (int)(g - row * GPR);
        float sv[16];
        if (gi * 16 + 16 <= KACT) {
            const float* p = src + row * KACT + gi * 16;
            #pragma unroll
            for (int q = 0; q < 4; q++) {
                float4 v = *(const float4*)(p + q*4);
                sv[q*4+0] = v.x; sv[q*4+1] = v.y; sv[q*4+2] = v.z; sv[q*4+3] = v.w;
            }
        } else {
            #pragma unroll
            for (int j = 0; j < 16; j++) {
                int k = gi * 16 + j;
                sv[j] = (k < KACT) ? src[row * KACT + k] : 0.f;
            }
        }
        __half2 o[8]; perm16(sv, o);
        hf* q = dst + g * 16;
        *(uint4*)q = *(uint4*)o;
        *(uint4*)(q + 8) = *(uint4*)(o + 4);
    }
}

// ---- fp16 GEMM: C[m,n] = epi( sum_k A[m,k]*W[n,k] )
// MODE 0 raw->Cf, 1 silu->Ch(intl half), 2 sigm->Cf, 5 mulAux->Cf
template <int MODE>
__global__ void __launch_bounds__(256, 2) k_gemm(
    const hf* __restrict__ A, int lda,
    const hf* __restrict__ W, int ldw, int Ntot, int KT,
    float* __restrict__ Cf, hf* __restrict__ Ch, int ldc,
    const float* __restrict__ Aux, int ldaux, int cntOv)
{
    extern __shared__ hf smh[];
    int e = blockIdx.z;
    int cnt = (cntOv >= 0) ? cntOv : g_cnt[e];
    int m0 = blockIdx.x * 128;
    if (m0 >= cnt) return;
    int n0 = blockIdx.y * 128;

    A += (size_t)e * CAP * lda;
    W += (size_t)e * Ntot * ldw;
    size_t co = (size_t)e * CAP * ldc;
    if (Cf) Cf += co;
    if (Ch) Ch += co;
    if (Aux) Aux += (size_t)e * CAP * ldaux;

    uint32_t sb = (uint32_t)__cvta_generic_to_shared(smh);
    int tid = threadIdx.x, warp = tid >> 5, lane = tid & 31;
    int wm = warp >> 1, wn = warp & 1;       // warp tile 32m x 64n
    int qr = lane >> 2, qc = lane & 3;

    float acc[2][8][4];
    #pragma unroll
    for (int mt = 0; mt < 2; mt++)
        #pragma unroll
        for (int nt = 0; nt < 8; nt++)
            #pragma unroll
            for (int q = 0; q < 4; q++) acc[mt][nt][q] = 0.f;

    auto load_stage = [&](int kt, int stg) {
        int k0 = kt * KC;
        #pragma unroll
        for (int s4 = 0; s4 < 4; s4++) {
            int f = tid + s4*256, r = f >> 3, c = f & 7;
            cp16(sb + stg*STG_B + r*160 + c*16, A + (size_t)(m0 + r)*lda + k0 + c*8, true);
        }
        #pragma unroll
        for (int s4 = 0; s4 < 4; s4++) {
            int f = tid + s4*256, r = f >> 3, c = f & 7;
            bool pr = (n0 + r) < Ntot;
            const hf* gp = W + (size_t)(n0 + r)*ldw + k0 + c*8;
            cp16(sb + stg*STG_B + 20480 + r*160 + c*16, pr ? gp : W, pr);
        }
        asm volatile("cp.async.commit_group;");
    };

    load_stage(0, 0);

    for (int kt = 0; kt < KT; kt++) {
        if (kt + 1 < KT) load_stage(kt + 1, (kt + 1) & 1);
        if (kt + 1 < KT) asm volatile("cp.async.wait_group 1;");
        else             asm volatile("cp.async.wait_group 0;");
        __syncthreads();

        int stg = kt & 1;
        const hf* Asm = smh + stg * (STG_B/2);
        const hf* Bsm = Asm + 10240;           // 128*80

        #pragma unroll
        for (int ks = 0; ks < 4; ks++) {
            int kb = ks * 16 + qc * 4;
            uint2 a0 = *(const uint2*)(Asm + (wm*32 + qr)*RSH + kb);
            uint2 a1 = *(const uint2*)(Asm + (wm*32 + qr + 8)*RSH + kb);
            uint2 a2 = *(const uint2*)(Asm + (wm*32 + 16 + qr)*RSH + kb);
            uint2 a3 = *(const uint2*)(Asm + (wm*32 + 16 + qr + 8)*RSH + kb);
            const hf* bp = Bsm + (wn*64 + qr)*RSH + kb;
            #pragma unroll
            for (int nt = 0; nt < 8; nt++) {
                uint2 bb = *(const uint2*)(bp + nt*8*RSH);
                mma16(acc[0][nt], a0.x, a1.x, a0.y, a1.y, bb.x, bb.y);
                mma16(acc[1][nt], a2.x, a3.x, a2.y, a3.y, bb.x, bb.y);
            }
        }
        __syncthreads();
    }

    #pragma unroll
    for (int mt = 0; mt < 2; mt++) {
        #pragma unroll
        for (int nt = 0; nt < 8; nt++) {
            int n = n0 + wn*64 + nt*8 + qc*2;
            #pragma unroll
            for (int half = 0; half < 2; half++) {
                int m = m0 + wm*32 + mt*16 + qr + half*8;
                if (m >= cnt) continue;
                float v0 = acc[mt][nt][half*2], v1 = acc[mt][nt][half*2 + 1];
                if (MODE == 0) {
                    if (n < Ntot) {
                        float2 s2 = {v0, v1};
                        *(float2*)(Cf + (size_t)m * ldc + n) = s2;
                    }
                } else if (MODE == 2) {
                    if (n < Ntot) {
                        float2 s2 = {1.f/(1.f+expf(-v0)), 1.f/(1.f+expf(-v1))};
                        *(float2*)(Cf + (size_t)m * ldc + n) = s2;
                    }
                } else if (MODE == 5) {
                    if (n < Ntot) {
                        float2 s2 = {v0 * Aux[(size_t)m*ldaux + n], v1 * Aux[(size_t)m*ldaux + n + 1]};
                        *(float2*)(Cf + (size_t)m * ldc + n) = s2;
                    }
                } else {  // MODE 1: silu -> interleaved half
                    if (n < Ntot) {
                        float x0 = v0/(1.f+expf(-v0)), x1 = v1/(1.f+expf(-v1));
                        size_t rowo = (size_t)m * ldc + (n & ~15);
                        *(__half2*)(Ch + rowo + posh(n & 15)) = __floats2half2_rn(x0, x1);
                    }
                }
            }
        }
    }
}

// ---- fused gate/up fp16 GEMM: P2 = silu(A@Wg^T)*(A@Wu^T) -> interleaved half ----
__global__ void __launch_bounds__(512, 1) k_gemmF(
    const hf* __restrict__ A,
    const hf* __restrict__ Wg, const hf* __restrict__ Wu,
    hf* __restrict__ Ch)
{
    extern __shared__ hf smh[];
    int e = blockIdx.z;
    int cnt = g_cnt[e];
    int m0 = blockIdx.x * 128;
    if (m0 >= cnt) return;
    int n0 = blockIdx.y * 128;

    A  += (size_t)e * CAP * DD;
    Wg += (size_t)e * DFFN * DD;
    Wu += (size_t)e * DFFN * DD;
    Ch += (size_t)e * CAP * LDP;

    uint32_t sb = (uint32_t)__cvta_generic_to_shared(smh);
    int tid = threadIdx.x, warp = tid >> 5, lane = tid & 31;
    int wm = warp >> 3, wn = warp & 7;       // 2m x 8n warps; warp tile 64m x 16n
    int qr = lane >> 2, qc = lane & 3;

    float accG[4][2][4], accU[4][2][4];
    #pragma unroll
    for (int mt = 0; mt < 4; mt++)
        #pragma unroll
        for (int nt = 0; nt < 2; nt++)
            #pragma unroll
            for (int q = 0; q < 4; q++) { accG[mt][nt][q] = 0.f; accU[mt][nt][q] = 0.f; }

    auto load_stage = [&](int kt, int stg) {
        int k0 = kt * KC;
        #pragma unroll
        for (int i = 0; i < 6; i++) {
            int f = tid + i*512, r = f >> 3, c = f & 7;
            const hf* gp; bool pr = true;
            if (r < 128) {
                gp = A + (size_t)(m0 + r)*DD + k0 + c*8;
            } else if (r < 256) {
                int nr = n0 + r - 128; pr = nr < DFFN;
                gp = pr ? (Wg + (size_t)nr*DD + k0 + c*8) : A;
            } else {
                int nr = n0 + r - 256; pr = nr < DFFN;
                gp = pr ? (Wu + (size_t)nr*DD + k0 + c*8) : A;
            }
            cp16(sb + stg*STG_BF + r*160 + c*16, gp, pr);
        }
        asm volatile("cp.async.commit_group;");
    };

    const int KT = DD / KC;
    load_stage(0, 0);

    for (int kt = 0; kt < KT; kt++) {
        if (kt + 1 < KT) load_stage(kt + 1, (kt + 1) & 1);
        if (kt + 1 < KT) asm volatile("cp.async.wait_group 1;");
        else             asm volatile("cp.async.wait_group 0;");
        __syncthreads();

        int stg = kt & 1;
        const hf* Asm = smh + stg * (STG_BF/2);
        const hf* Gsm = Asm + 10240;
        const hf* Usm = Asm + 20480;

        #pragma unroll
        for (int ks = 0; ks < 4; ks++) {
            int kb = ks * 16 + qc * 4;
            uint2 al[4], ah[4];
            #pragma unroll
            for (int mt = 0; mt < 4; mt++) {
                al[mt] = *(const uint2*)(Asm + (wm*64 + mt*16 + qr)*RSH + kb);
                ah[mt] = *(const uint2*)(Asm + (wm*64 + mt*16 + qr + 8)*RSH + kb);
            }
            #pragma unroll
            for (int nt = 0; nt < 2; nt++) {
                int br = (wn*16 + nt*8 + qr)*RSH + kb;
                uint2 bg = *(const uint2*)(Gsm + br);
                uint2 bu = *(const uint2*)(Usm + br);
                #pragma unroll
                for (int mt = 0; mt < 4; mt++) {
                    mma16(accG[mt][nt], al[mt].x, ah[mt].x, al[mt].y, ah[mt].y, bg.x, bg.y);
                    mma16(accU[mt][nt], al[mt].x, ah[mt].x, al[mt].y, ah[mt].y, bu.x, bu.y);
                }
            }
        }
        __syncthreads();
    }

    #pragma unroll
    for (int mt = 0; mt < 4; mt++) {
        #pragma unroll
        for (int nt = 0; nt < 2; nt++) {
            int n = n0 + wn*16 + nt*8 + qc*2;
            #pragma unroll
            for (int half = 0; half < 2; half++) {
                int m = m0 + wm*64 + mt*16 + qr + half*8;
                if (m >= cnt) continue;
                size_t rowo = (size_t)m * LDP + (n & ~15);
                int p0 = posh(n & 15);
                if (n < DFFN) {
                    float gv0 = accG[mt][nt][half*2], gv1 = accG[mt][nt][half*2 + 1];
                    float uv0 = accU[mt][nt][half*2], uv1 = accU[mt][nt][half*2 + 1];
                    float x0 = (gv0/(1.f+expf(-gv0))) * uv0;
                    float x1 = (gv1/(1.f+expf(-gv1))) * uv1;
                    *(__half2*)(Ch + rowo + p0) = __floats2half2_rn(x0, x1);
                } else if (n < LDP) {
                    *(__half2*)(Ch + rowo + p0) = __floats2half2_rn(0.f, 0.f);
                }
            }
        }
    }
}

// ---- per active pair: gates, sinkhorn, h, hn (half interleaved) ----
__global__ void __launch_bounds__(128) k_hn(const float* __restrict__ stream,
                                            const float* __restrict__ b_pre,
                                            const float* __restrict__ b_post,
                                            const float* __restrict__ b_res,
                                            const float* __restrict__ alpha_pre,
                                            const float* __restrict__ alpha_post,
                                            const float* __restrict__ alpha_res,
                                            const float* __restrict__ sw_norm_w)
{
    int row = blockIdx.x, e = blockIdx.y;
    if (row >= g_cnt[e]) return;
    int token = g_tok[e*CAP + row], b = token / TT, t = token % TT, tid = threadIdx.x;
    __shared__ float hpre[NS], red2[4];

    if (tid == 0) {
        const float* d = g_dots + (size_t)token*384 + e*24;
        size_t slot = (size_t)e*CAP + row;
        float ap = alpha_pre[e], ao = alpha_post[e], ar = alpha_res[e];
        #pragma unroll
        for (int i = 0; i < NS; i++)
            hpre[i] = 1.f / (1.f + expf(-(ap*d[i] + b_pre[e*NS+i])));
        #pragma unroll
        for (int i = 0; i < NS; i++)
            g_Hpost[slot*NS+i] = 2.f / (1.f + expf(-(ao*d[4+i] + b_post[e*NS+i])));
        float M[16];
        #pragma unroll
        for (int k = 0; k < 16; k++) M[k] = expf(ar*d[8+k] + b_res[e*16+k]);
        for (int it = 0; it < 6; it++) {
            #pragma unroll
            for (int i = 0; i < 4; i++) {
                float ir = 1.f / (M[i*4]+M[i*4+1]+M[i*4+2]+M[i*4+3]);
                M[i*4]*=ir; M[i*4+1]*=ir; M[i*4+2]*=ir; M[i*4+3]*=ir;
            }
            #pragma unroll
            for (int j = 0; j < 4; j++) {
                float ic = 1.f / (M[j]+M[4+j]+M[8+j]+M[12+j]);
                M[j]*=ic; M[4+j]*=ic; M[8+j]*=ic; M[12+j]*=ic;
            }
        }
        #pragma unroll
        for (int k = 0; k < 16; k++) g_Hres[slot*16+k] = M[k];
    }
    __syncthreads();

    const float* sp0 = stream + ((size_t)b*NS*TT + t) * DD;
    float h0 = hpre[0], h1 = hpre[1], h2 = hpre[2], h3 = hpre[3];
    float hreg[8], hq = 0.f;
    #pragma unroll
    for (int u = 0; u < 8; u++) {
        int dd = tid + u*128;
        float h = h0*sp0[dd] + h1*sp0[(size_t)TT*DD+dd]
                + h2*sp0[2*(size_t)TT*DD+dd] + h3*sp0[3*(size_t)TT*DD+dd];
        hreg[u] = h; hq += h*h;
    }
    int lane = tid & 31, warp = tid >> 5;
    #pragma unroll
    for (int o = 16; o > 0; o >>= 1) hq += __shfl_down_sync(0xffffffffu, hq, o);
    if (lane == 0) red2[warp] = hq;
    __syncthreads();
    if (tid == 0) red2[0] = rsqrtf((red2[0]+red2[1]+red2[2]+red2[3]) / (float)DD + EPS_F);
    __syncthreads();
    float sh = red2[0];
    const float* snw = sw_norm_w + (size_t)e*DD;
    hf* hn = g_HN + ((size_t)e*CAP + row) * DD;
    #pragma unroll
    for (int u = 0; u < 8; u++) {
        int dd = tid + u*128;
        float v = hreg[u] * sh * snw[dd];
        hn[(dd & ~15) + posh(dd & 15)] = __float2half_rn(v);
    }
}

// ---- combine res + post ----
__global__ void __launch_bounds__(128) k_out(const float* __restrict__ stream,
                                             float* __restrict__ outp)
{
    int token = blockIdx.x, b = token / TT, t = token % TT, tid = threadIdx.x;
    const float* sp0 = stream + ((size_t)b*NS*TT + t) * DD;
    float st[4][8], acc[4][8];
    #pragma unroll
    for (int i = 0; i < 4; i++)
        #pragma unroll
        for (int j = 0; j < 8; j++) {
            st[i][j] = sp0[(size_t)i*TT*DD + tid + j*128];
            acc[i][j] = 0.f;
        }
    for (int e = 0; e < EE; e++) {
        int row = g_row[token*EE + e];
        if (row < 0) continue;
        float g = g_gatev[token*EE + e];
        size_t slot = (size_t)e*CAP + row;
        float Hr[16], Hp[4];
        #pragma unroll
        for (int k = 0; k < 16; k++) Hr[k] = g_Hres[slot*16+k];
        #pragma unroll
        for (int i = 0; i < 4; i++) Hp[i] = g_Hpost[slot*4+i];
        const float* o = g_OUT + slot*DD;
        #pragma unroll
        for (int j = 0; j < 8; j++) {
            float ov = o[tid + j*128];
            #pragma unroll
            for (int i = 0; i < 4; i++) {
                float r = Hr[i*4]*st[0][j] + Hr[i*4+1]*st[1][j]
                        + Hr[i*4+2]*st[2][j] + Hr[i*4+3]*st[3][j];
                acc[i][j] += g * (r + Hp[i]*ov);
            }
        }
    }
    #pragma unroll
    for (int i = 0; i < 4; i++)
        #pragma unroll
        for (int j = 0; j < 8; j++)
            outp[((size_t)(b*NS+i)*TT + t)*DD + tid + j*128] = acc[i][j];
}

#define GSA(p, s) cudaGetSymbolAddress((void**)&p, s)

extern "C" void kernel_launch(void* const* d_in, const int* in_sizes, int n_in,
                              void* d_out, int out_size)
{
    (void)in_sizes; (void)n_in; (void)out_size;
    const float* stream   = (const float*)d_in[0];
    const float* router_w = (const float*)d_in[1];
    const float* mhc      = (const float*)d_in[2];
    const float* phi_pre  = (const float*)d_in[3];
    const float* phi_post = (const float*)d_in[4];
    const float* phi_res  = (const float*)d_in[5];
    const float* b_pre    = (const float*)d_in[6];
    const float* b_post   = (const float*)d_in[7];
    const float* b_res    = (const float*)d_in[8];
    const float* a_pre    = (const float*)d_in[9];
    const float* a_post   = (const float*)d_in[10];
    const float* a_res    = (const float*)d_in[11];
    const float* sw_nw    = (const float*)d_in[12];
    const float* wd_w     = (const float*)d_in[13];
    const float* wu_w     = (const float*)d_in[14];
    const float* gate_w   = (const float*)d_in[15];
    const float* up_w     = (const float*)d_in[16];
    const float* down_w   = (const float*)d_in[17];

    float* outp = (float*)d_out;
    float* out_gate = outp + (size_t)BB*NS*TT*DD;

    cudaFuncSetAttribute(k_gemm<0>, cudaFuncAttributeMaxDynamicSharedMemorySize, SMEM_DYN);
    cudaFuncSetAttribute(k_gemm<1>, cudaFuncAttributeMaxDynamicSharedMemorySize, SMEM_DYN);
    cudaFuncSetAttribute(k_gemm<2>, cudaFuncAttributeMaxDynamicSharedMemorySize, SMEM_DYN);
    cudaFuncSetAttribute(k_gemm<5>, cudaFuncAttributeMaxDynamicSharedMemorySize, SMEM_DYN);
    cudaFuncSetAttribute(k_gemmF, cudaFuncAttributeMaxDynamicSharedMemorySize, SMEM_F);

    hf *base, *HN, *T1, *P2, *phiW, *wd, *wu, *gt, *up, *dn;
    float *GS, *OUT, *dots;
    GSA(base, g_base); GSA(HN, g_HN); GSA(T1, g_T1); GSA(P2, g_P2);
    GSA(phiW, g_phiW); GSA(wd, g_wd); GSA(wu, g_wu); GSA(gt, g_gt);
    GSA(up, g_up); GSA(dn, g_dn);
    GSA(GS, g_GS); GSA(OUT, g_OUT); GSA(dots, g_dots);

    k_zero<<<1, 32>>>();
    k_gate<<<BT, 256>>>(stream, router_w, out_gate);
    k_base<<<BT, 256>>>(stream);
    k_pack<<<(EE*24*NDIM/16)/256, 256>>>(mhc, phi_pre, phi_post, phi_res);
    {
        long n1 = (long)EE*DD*DD/16;
        long n2 = (long)EE*DFFN*DD/16;
        long n3 = (long)EE*DD*LDP/16;
        unsigned b1 = (unsigned)((n1 + 1023) / 1024);
        unsigned b2 = (unsigned)((n2 + 1023) / 1024);
        unsigned b3 = (unsigned)((n3 + 1023) / 1024);
        k_packw16<DD, DD><<<b1, 256>>>(wd_w, wd, n1);
        k_packw16<DD, DD><<<b1, 256>>>(wu_w, wu, n1);
        k_packw16<DD, DD><<<b2, 256>>>(gate_w, gt, n2);
        k_packw16<DD, DD><<<b2, 256>>>(up_w, up, n2);
        k_packw16<DFFN, LDP><<<b3, 256>>>(down_w, dn, n3);
    }

    // dots = base @ phiW^T  (N=384, K=4096)
    k_gemm<0><<<dim3(32,3,1), 256, SMEM_DYN>>>(base, NDIM, phiW, NDIM, 384, NDIM/KC,
                                               dots, (hf*)0, 384, (const float*)0, 0, BT);

    k_hn<<<dim3(CAP, EE), 128>>>(stream, b_pre, b_post, b_res, a_pre, a_post, a_res, sw_nw);

    dim3 gD(32, 8, EE);

    // T1 = silu(HN @ wd^T) -> interleaved half
    k_gemm<1><<<gD, 256, SMEM_DYN>>>(HN, DD, wd, DD, DD, DD/KC,
                                     (float*)0, T1, DD, (const float*)0, 0, -1);
    // GS = sigmoid(T1 @ wu^T) -> f32
    k_gemm<2><<<gD, 256, SMEM_DYN>>>(T1, DD, wu, DD, DD, DD/KC,
                                     GS, (hf*)0, DD, (const float*)0, 0, -1);
    // P2 = silu(HN @ gt^T) * (HN @ up^T) -> interleaved half (pad to LDP)
    k_gemmF<<<dim3(32,13,EE), 512, SMEM_F>>>(HN, gt, up, P2);
    // OUT = (P2 @ dn^T) * GS -> f32
    k_gemm<5><<<gD, 256, SMEM_DYN>>>(P2, LDP, dn, LDP, DD, LDP/KC,
                                     OUT, (hf*)0, DD, GS, DD, -1);

    k_out<<<BT, 128>>>(stream, outp);
}

// round 12
// speedup vs baseline: 2.5170x; 1.0051x over previous
#include <cuda_runtime.h>
#include <cuda_fp16.h>
#include <math.h>
#include <stdint.h>

#define BB 2
#define NS 4
#define TT 2048
#define DD 1024
#define EE 16
#define NDIM 4096
#define DFFN 1656
#define LDP 1664
#define BT (BB*TT)
#define CAP BT
#define EPS_F 1.1920929e-7f
#define RSH 80
#define KC 64
#define STG_B 40960
#define SMEM_DYN (2*STG_B)
#define STG_BF 61440
#define SMEM_F (2*STG_BF)

typedef __half hf;

// ---- device scratch ----
__device__ __align__(16) hf g_base[(size_t)BT*NDIM];
__device__ __align__(16) hf g_HN [(size_t)EE*CAP*DD];
__device__ __align__(16) hf g_T1 [(size_t)EE*CAP*DD];
__device__ __align__(16) hf g_P2 [(size_t)EE*CAP*LDP];
__device__ __align__(16) hf g_phiW[(size_t)EE*24*NDIM];
__device__ __align__(16) hf g_wd[(size_t)EE*DD*DD];
__device__ __align__(16) hf g_wu[(size_t)EE*DD*DD];
__device__ __align__(16) hf g_gt[(size_t)EE*DFFN*DD];
__device__ __align__(16) hf g_up[(size_t)EE*DFFN*DD];
__device__ __align__(16) hf g_dn[(size_t)EE*DD*LDP];
__device__ __align__(16) float g_GS [(size_t)EE*CAP*DD];
__device__ __align__(16) float g_OUT[(size_t)EE*CAP*DD];
__device__ __align__(16) float g_dots[(size_t)BT*384];
__device__ int   g_row[BT*EE];
__device__ float g_gatev[BT*EE];
__device__ int   g_cnt[EE];
__device__ float g_Hpost[(size_t)EE*CAP*NS];
__device__ float g_Hres[(size_t)EE*CAP*16];

// pack segment boundaries (groups of 16 elements)
#define N1G 1048576L            // EE*DD*DD/16   (wd, wu)
#define N2G 1695744L            // EE*DFFN*DD/16 (gt, up)
#define N3G 1703936L            // EE*DD*LDP/16  (dn)
#define NTOTG (2*N1G + 2*N2G + N3G)

// ---- helpers ----
__device__ __forceinline__ int posh(int n) {
    return ((n >> 1) & 3) * 4 + ((n >> 3) & 1) * 2 + (n & 1);
}
__device__ __forceinline__ void perm16(const float* s, __half2* o) {
    const int pr[8] = {0, 8, 2, 10, 4, 12, 6, 14};
    #pragma unroll
    for (int j = 0; j < 8; j++)
        o[j] = __floats2half2_rn(s[pr[j]], s[pr[j] + 1]);
}
__device__ __forceinline__ void mma16(float* c, uint32_t a0, uint32_t a1, uint32_t a2,
                                      uint32_t a3, uint32_t b0, uint32_t b1) {
    asm volatile(
        "mma.sync.aligned.m16n8k16.row.col.f32.f16.f16.f32 "
        "{%0,%1,%2,%3}, {%4,%5,%6,%7}, {%8,%9}, {%0,%1,%2,%3};"
        : "+f"(c[0]), "+f"(c[1]), "+f"(c[2]), "+f"(c[3])
        : "r"(a0), "r"(a1), "r"(a2), "r"(a3), "r"(b0), "r"(b1));
}
__device__ __forceinline__ void cp16(uint32_t s, const void* g, bool pr) {
    int b = pr ? 16 : 0;
    asm volatile("cp.async.cg.shared.global [%0], [%1], 16, %2;" :: "r"(s), "l"(g), "r"(b));
}

__global__ void k_zero() { if (threadIdx.x < EE) g_cnt[threadIdx.x] = 0; }

__device__ int g_tok[EE*CAP];

// ---- router gate + token rms + base emit (fused) ----
__global__ void __launch_bounds__(256) k_gate(const float* __restrict__ stream,
                                              const float* __restrict__ router_w,
                                              float* __restrict__ out_gate)
{
    int token = blockIdx.x, b = token / TT, t = token % TT, tid = threadIdx.x;
    __shared__ float route[DD], red[256], logit[EE];
    const float* sp0 = stream + ((size_t)b * NS * TT + t) * DD;
    float v[4][4];                    // [iter][streamidx]
    float ss = 0.f;
    #pragma unroll
    for (int it = 0; it < 4; it++) {
        int dd = tid + it * 256;
        float v0 = sp0[dd], v1 = sp0[(size_t)TT*DD + dd];
        float v2 = sp0[2*(size_t)TT*DD + dd], v3 = sp0[3*(size_t)TT*DD + dd];
        v[it][0] = v0; v[it][1] = v1; v[it][2] = v2; v[it][3] = v3;
        ss += v0*v0 + v1*v1 + v2*v2 + v3*v3;
        route[dd] = 0.25f * (v0 + v1 + v2 + v3);
    }
    red[tid] = ss; __syncthreads();
    for (int s = 128; s > 0; s >>= 1) { if (tid < s) red[tid] += red[tid+s]; __syncthreads(); }
    float srms = rsqrtf(red[0] / (float)NDIM + EPS_F);

    // emit base (interleaved half) while logits compute
    hf* dst = g_base + (size_t)token * NDIM;
    #pragma unroll
    for (int it = 0; it < 4; it++) {
        int dd = tid + it * 256;
        #pragma unroll
        for (int i = 0; i < 4; i++) {
            int j = i * 1024 + dd;
            dst[(j & ~15) | posh(j & 15)] = __float2half_rn(v[it][i] * srms);
        }
    }

    int warp = tid >> 5, lane = tid & 31;
    for (int e = warp; e < EE; e += 8) {
        const float* rw = router_w + (size_t)e * DD;
        float acc = 0.f;
        for (int dd = lane; dd < DD; dd += 32) acc += route[dd] * rw[dd];
        #pragma unroll
        for (int o = 16; o > 0; o >>= 1) acc += __shfl_down_sync(0xffffffffu, acc, o);
        if (lane == 0) logit[e] = acc;
    }
    __syncthreads();
    if (tid == 0) {
        float p[EE], mx = -1e30f;
        #pragma unroll
        for (int e = 0; e < EE; e++) mx = fmaxf(mx, logit[e]);
        float sum = 0.f;
        #pragma unroll
        for (int e = 0; e < EE; e++) { p[e] = expf(logit[e] - mx); sum += p[e]; }
        float inv = 1.f / sum;
        #pragma unroll
        for (int e = 0; e < EE; e++) p[e] *= inv;
        int ord[EE];
        #pragma unroll
        for (int e = 0; e < EE; e++) ord[e] = e;
        for (int i = 1; i < EE; i++) {
            int oi = ord[i]; float pi = p[oi]; int j = i - 1;
            while (j >= 0 && p[ord[j]] < pi) { ord[j+1] = ord[j]; j--; }
            ord[j+1] = oi;
        }
        float cum = 0.f, gate[EE];
        #pragma unroll
        for (int e = 0; e < EE; e++) gate[e] = 0.f;
        for (int r = 0; r < EE; r++) {
            int e = ord[r];
            if ((r == 0) || (cum < 0.8f && r < 4)) gate[e] = p[e];
            cum += p[e];
        }
        for (int e = 0; e < EE; e++) {
            float g = gate[e];
            out_gate[(size_t)token*EE + e] = g;
            g_gatev[token*EE + e] = g;
            int row = -1;
            if (g > 0.f) { row = atomicAdd(&g_cnt[e], 1); g_tok[e*CAP + row] = token; }
            g_row[token*EE + e] = row;
        }
    }
}

// ---- phi weights pack (fold mhc norm) ----
__global__ void __launch_bounds__(256) k_pack(const float* __restrict__ mhc_norm_w,
                                              const float* __restrict__ pw,
                                              const float* __restrict__ ow,
                                              const float* __restrict__ rw)
{
    int g = blockIdx.x * 256 + threadIdx.x;
    int e = g / 6144;
    int rem = g - e * 6144;
    int r = rem >> 8;
    int j0 = (rem & 255) * 16;
    const float* wsrc;
    if (r < 4)      wsrc = pw + ((size_t)e*4 + r)*NDIM + j0;
    else if (r < 8) wsrc = ow + ((size_t)e*4 + (r-4))*NDIM + j0;
    else            wsrc = rw + ((size_t)e*16 + (r-8))*NDIM + j0;
    const float* nsrc = mhc_norm_w + (size_t)e*NDIM + j0;
    float sv[16];
    #pragma unroll
    for (int q = 0; q < 4; q++) {
        float4 w = *(const float4*)(wsrc + q*4);
        float4 n = *(const float4*)(nsrc + q*4);
        sv[q*4+0] = w.x*n.x; sv[q*4+1] = w.y*n.y; sv[q*4+2] = w.z*n.z; sv[q*4+3] = w.w*n.w;
    }
    __half2 o[8]; perm16(sv, o);
    hf* q = g_phiW + (size_t)g * 16;
    *(uint4*)q = *(uint4*)o;
    *(uint4*)(q + 8) = *(uint4*)(o + 4);
}

// ---- merged weight pack: all 5 weights, one grid-stride kernel ----
__device__ __forceinline__ void packgrp(const float* p, hf* q) {
    float sv[16];
    #pragma unroll
    for (int c = 0; c < 4; c++) {
        float4 v = *(const float4*)(p + c*4);
        sv[c*4+0] = v.x; sv[c*4+1] = v.y; sv[c*4+2] = v.z; sv[c*4+3] = v.w;
    }
    __half2 o[8]; perm16(sv, o);
    *(uint4*)q = *(uint4*)o;
    *(uint4*)(q + 8) = *(uint4*)(o + 4);
}
__global__ void __launch_bounds__(256) k_packall(const float* __restrict__ wd_w,
                                                 const float* __restrict__ wu_w,
                                                 const float* __restrict__ gate_w,
                                                 const float* __restrict__ up_w,
                                                 const float* __restrict__ down_w)
{
    long g0 = (long)blockIdx.x * 256 + threadIdx.x;
    long stride = (long)gridDim.x * 256;
    for (long g = g0; g < NTOTG; g += stride) {
        if (g < 2*N1G) {                       // wd / wu : K=1024, GPR=64
            long l = (g < N1G) ? g : g - N1G;
            const float* src = (g < N1G) ? wd_w : wu_w;
            hf* dst = (g < N1G) ? g_wd : g_wu;
            long row = l >> 6; int gi = (int)(l & 63);
            packgrp(src + row * DD + gi * 16, dst + l * 16);
        } else if (g < 2*N1G + 2*N2G) {        // gt / up : K=1024, GPR=64
            long l = g - 2*N1G;
            const float* src = (l < N2G) ? gate_w : up_w;
            hf* dst = (l < N2G) ? g_gt : g_up;
            if (l >= N2G) l -= N2G;
            long row = l >> 6; int gi = (int)(l & 63);
            packgrp(src + row * DD + gi * 16, dst + l * 16);
        } else {                               // dn : KACT=1656, KPAD=1664, GPR=104
            long l = g - 2*N1G - 2*N2G;
            long row = l / 104; int gi = (int)(l - row * 104);
            hf* q = g_dn + l * 16;
            if (gi * 16 + 16 <= DFFN) {
                packgrp(down_w + row * DFFN + gi * 16, q);
            } else {
                float sv[16];
                #pragma unroll
                for (int j = 0; j < 16; j++) {
                    int k = gi * 16 + j;
                    sv[j] = (k < DFFN) ? down_w[row * DFFN + k] : 0.f;
                }
                __half2 o[8]; perm16(sv, o);
                *(uint4*)q = *(uint4*)o;
                *(uint4*)(q + 8) = *(uint4*)(o + 4);
            }
        }
    }
}

// ---- fp16 GEMM (unchanged from R11) ----
template <int MODE>
__global__ void __launch_bounds__(256, 2) k_gemm(
    const hf* __restrict__ A, int lda,
    const hf* __restrict__ W, int ldw, int Ntot, int KT,
    float* __restrict__ Cf, hf* __restrict__ Ch, int ldc,
    const float* __restrict__ Aux, int ldaux, int cntOv)
{
    extern __shared__ hf smh[];
    int e = blockIdx.z;
    int cnt = (cntOv >= 0) ? cntOv : g_cnt[e];
    int m0 = blockIdx.x * 128;
    if (m0 >= cnt) return;
    int n0 = blockIdx.y * 128;

    A += (size_t)e * CAP * lda;
    W += (size_t)e * Ntot * ldw;
    size_t co = (size_t)e * CAP * ldc;
    if (Cf) Cf += co;
    if (Ch) Ch += co;
    if (Aux) Aux += (size_t)e * CAP * ldaux;

    uint32_t sb = (uint32_t)__cvta_generic_to_shared(smh);
    int tid = threadIdx.x, warp = tid >> 5, lane = tid & 31;
    int wm = warp >> 1, wn = warp & 1;
    int qr = lane >> 2, qc = lane & 3;

    float acc[2][8][4];
    #pragma unroll
    for (int mt = 0; mt < 2; mt++)
        #pragma unroll
        for (int nt = 0; nt < 8; nt++)
            #pragma unroll
            for (int q = 0; q < 4; q++) acc[mt][nt][q] = 0.f;

    auto load_stage = [&](int kt, int stg) {
        int k0 = kt * KC;
        #pragma unroll
        for (int s4 = 0; s4 < 4; s4++) {
            int f = tid + s4*256, r = f >> 3, c = f & 7;
            cp16(sb + stg*STG_B + r*160 + c*16, A + (size_t)(m0 + r)*lda + k0 + c*8, true);
        }
        #pragma unroll
        for (int s4 = 0; s4 < 4; s4++) {
            int f = tid + s4*256, r = f >> 3, c = f & 7;
            bool pr = (n0 + r) < Ntot;
            const hf* gp = W + (size_t)(n0 + r)*ldw + k0 + c*8;
            cp16(sb + stg*STG_B + 20480 + r*160 + c*16, pr ? gp : W, pr);
        }
        asm volatile("cp.async.commit_group;");
    };

    load_stage(0, 0);

    for (int kt = 0; kt < KT; kt++) {
        if (kt + 1 < KT) load_stage(kt + 1, (kt + 1) & 1);
        if (kt + 1 < KT) asm volatile("cp.async.wait_group 1;");
        else             asm volatile("cp.async.wait_group 0;");
        __syncthreads();

        int stg = kt & 1;
        const hf* Asm = smh + stg * (STG_B/2);
        const hf* Bsm = Asm + 10240;

        #pragma unroll
        for (int ks = 0; ks < 4; ks++) {
            int kb = ks * 16 + qc * 4;
            uint2 a0 = *(const uint2*)(Asm + (wm*32 + qr)*RSH + kb);
            uint2 a1 = *(const uint2*)(Asm + (wm*32 + qr + 8)*RSH + kb);
            uint2 a2 = *(const uint2*)(Asm + (wm*32 + 16 + qr)*RSH + kb);
            uint2 a3 = *(const uint2*)(Asm + (wm*32 + 16 + qr + 8)*RSH + kb);
            const hf* bp = Bsm + (wn*64 + qr)*RSH + kb;
            #pragma unroll
            for (int nt = 0; nt < 8; nt++) {
                uint2 bb = *(const uint2*)(bp + nt*8*RSH);
                mma16(acc[0][nt], a0.x, a1.x, a0.y, a1.y, bb.x, bb.y);
                mma16(acc[1][nt], a2.x, a3.x, a2.y, a3.y, bb.x, bb.y);
            }
        }
        __syncthreads();
    }

    #pragma unroll
    for (int mt = 0; mt < 2; mt++) {
        #pragma unroll
        for (int nt = 0; nt < 8; nt++) {
            int n = n0 + wn*64 + nt*8 + qc*2;
            #pragma unroll
            for (int half = 0; half < 2; half++) {
                int m = m0 + wm*32 + mt*16 + qr + half*8;
                if (m >= cnt) continue;
                float v0 = acc[mt][nt][half*2], v1 = acc[mt][nt][half*2 + 1];
                if (MODE == 0) {
                    if (n < Ntot) {
                        float2 s2 = {v0, v1};
                        *(float2*)(Cf + (size_t)m * ldc + n) = s2;
                    }
                } else if (MODE == 2) {
                    if (n < Ntot) {
                        float2 s2 = {1.f/(1.f+expf(-v0)), 1.f/(1.f+expf(-v1))};
                        *(float2*)(Cf + (size_t)m * ldc + n) = s2;
                    }
                } else if (MODE == 5) {
                    if (n < Ntot) {
                        float2 s2 = {v0 * Aux[(size_t)m*ldaux + n], v1 * Aux[(size_t)m*ldaux + n + 1]};
                        *(float2*)(Cf + (size_t)m * ldc + n) = s2;
                    }
                } else {
                    if (n < Ntot) {
                        float x0 = v0/(1.f+expf(-v0)), x1 = v1/(1.f+expf(-v1));
                        size_t rowo = (size_t)m * ldc + (n & ~15);
                        *(__half2*)(Ch + rowo + posh(n & 15)) = __floats2half2_rn(x0, x1);
                    }
                }
            }
        }
    }
}

// ---- fused gate/up fp16 GEMM (unchanged from R11) ----
__global__ void __launch_bounds__(512, 1) k_gemmF(
    const hf* __restrict__ A,
    const hf* __restrict__ Wg, const hf* __restrict__ Wu,
    hf* __restrict__ Ch)
{
    extern __shared__ hf smh[];
    int e = blockIdx.z;
    int cnt = g_cnt[e];
    int m0 = blockIdx.x * 128;
    if (m0 >= cnt) return;
    int n0 = blockIdx.y * 128;

    A  += (size_t)e * CAP * DD;
    Wg += (size_t)e * DFFN * DD;
    Wu += (size_t)e * DFFN * DD;
    Ch += (size_t)e * CAP * LDP;

    uint32_t sb = (uint32_t)__cvta_generic_to_shared(smh);
    int tid = threadIdx.x, warp = tid >> 5, lane = tid & 31;
    int wm = warp >> 3, wn = warp & 7;
    int qr = lane >> 2, qc = lane & 3;

    float accG[4][2][4], accU[4][2][4];
    #pragma unroll
    for (int mt = 0; mt < 4; mt++)
        #pragma unroll
        for (int nt = 0; nt < 2; nt++)
            #pragma unroll
            for (int q = 0; q < 4; q++) { accG[mt][nt][q] = 0.f; accU[mt][nt][q] = 0.f; }

    auto load_stage = [&](int kt, int stg) {
        int k0 = kt * KC;
        #pragma unroll
        for (int i = 0; i < 6; i++) {
            int f = tid + i*512, r = f >> 3, c = f & 7;
            const hf* gp; bool pr = true;
            if (r < 128) {
                gp = A + (size_t)(m0 + r)*DD + k0 + c*8;
            } else if (r < 256) {
                int nr = n0 + r - 128; pr = nr < DFFN;
                gp = pr ? (Wg + (size_t)nr*DD + k0 + c*8) : A;
            } else {
                int nr = n0 + r - 256; pr = nr < DFFN;
                gp = pr ? (Wu + (size_t)nr*DD + k0 + c*8) : A;
            }
            cp16(sb + stg*STG_BF + r*160 + c*16, gp, pr);
        }
        asm volatile("cp.async.commit_group;");
    };

    const int KT = DD / KC;
    load_stage(0, 0);

    for (int kt = 0; kt < KT; kt++) {
        if (kt + 1 < KT) load_stage(kt + 1, (kt + 1) & 1);
        if (kt + 1 < KT) asm volatile("cp.async.wait_group 1;");
        else             asm volatile("cp.async.wait_group 0;");
        __syncthreads();

        int stg = kt & 1;
        const hf* Asm = smh + stg * (STG_BF/2);
        const hf* Gsm = Asm + 10240;
        const hf* Usm = Asm + 20480;

        #pragma unroll
        for (int ks = 0; ks < 4; ks++) {
            int kb = ks * 16 + qc * 4;
            uint2 al[4], ah[4];
            #pragma unroll
            for (int mt = 0; mt < 4; mt++) {
                al[mt] = *(const uint2*)(Asm + (wm*64 + mt*16 + qr)*RSH + kb);
                ah[mt] = *(const uint2*)(Asm + (wm*64 + mt*16 + qr + 8)*RSH + kb);
            }
            #pragma unroll
            for (int nt = 0; nt < 2; nt++) {
                int br = (wn*16 + nt*8 + qr)*RSH + kb;
                uint2 bg = *(const uint2*)(Gsm + br);
                uint2 bu = *(const uint2*)(Usm + br);
                #pragma unroll
                for (int mt = 0; mt < 4; mt++) {
                    mma16(accG[mt][nt], al[mt].x, ah[mt].x, al[mt].y, ah[mt].y, bg.x, bg.y);
                    mma16(accU[mt][nt], al[mt].x, ah[mt].x, al[mt].y, ah[mt].y, bu.x, bu.y);
                }
            }
        }
        __syncthreads();
    }

    #pragma unroll
    for (int mt = 0; mt < 4; mt++) {
        #pragma unroll
        for (int nt = 0; nt < 2; nt++) {
            int n = n0 + wn*16 + nt*8 + qc*2;
            #pragma unroll
            for (int half = 0; half < 2; half++) {
                int m = m0 + wm*64 + mt*16 + qr + half*8;
                if (m >= cnt) continue;
                size_t rowo = (size_t)m * LDP + (n & ~15);
                int p0 = posh(n & 15);
                if (n < DFFN) {
                    float gv0 = accG[mt][nt][half*2], gv1 = accG[mt][nt][half*2 + 1];
                    float uv0 = accU[mt][nt][half*2], uv1 = accU[mt][nt][half*2 + 1];
                    float x0 = (gv0/(1.f+expf(-gv0))) * uv0;
                    float x1 = (gv1/(1.f+expf(-gv1))) * uv1;
                    *(__half2*)(Ch + rowo + p0) = __floats2half2_rn(x0, x1);
                } else if (n < LDP) {
                    *(__half2*)(Ch + rowo + p0) = __floats2half2_rn(0.f, 0.f);
                }
            }
        }
    }
}

// ---- per-token: gates, sinkhorn, h, hn for all active experts ----
__global__ void __launch_bounds__(128) k_hn(const float* __restrict__ stream,
                                            const float* __restrict__ b_pre,
                                            const float* __restrict__ b_post,
                                            const float* __restrict__ b_res,
                                            const float* __restrict__ alpha_pre,
                                            const float* __restrict__ alpha_post,
                                            const float* __restrict__ alpha_res,
                                            const float* __restrict__ sw_norm_w)
{
    int token = blockIdx.x, b = token / TT, t = token % TT, tid = threadIdx.x;
    __shared__ float hpre[NS], red2[4];
    int lane = tid & 31, warp = tid >> 5;

    const float* sp0 = stream + ((size_t)b*NS*TT + t) * DD;
    float st[4][8];
    #pragma unroll
    for (int i = 0; i < 4; i++)
        #pragma unroll
        for (int u = 0; u < 8; u++)
            st[i][u] = sp0[(size_t)i*TT*DD + tid + u*128];

    for (int e = 0; e < EE; e++) {
        int row = g_row[token*EE + e];
        if (row < 0) continue;
        __syncthreads();
        if (tid == 0) {
            const float* d = g_dots + (size_t)token*384 + e*24;
            size_t slot = (size_t)e*CAP + row;
            float ap = alpha_pre[e], ao = alpha_post[e], ar = alpha_res[e];
            #pragma unroll
            for (int i = 0; i < NS; i++)
                hpre[i] = 1.f / (1.f + expf(-(ap*d[i] + b_pre[e*NS+i])));
            #pragma unroll
            for (int i = 0; i < NS; i++)
                g_Hpost[slot*NS+i] = 2.f / (1.f + expf(-(ao*d[4+i] + b_post[e*NS+i])));
            float M[16];
            #pragma unroll
            for (int k = 0; k < 16; k++) M[k] = expf(ar*d[8+k] + b_res[e*16+k]);
            for (int it = 0; it < 6; it++) {
                #pragma unroll
                for (int i = 0; i < 4; i++) {
                    float ir = 1.f / (M[i*4]+M[i*4+1]+M[i*4+2]+M[i*4+3]);
                    M[i*4]*=ir; M[i*4+1]*=ir; M[i*4+2]*=ir; M[i*4+3]*=ir;
                }
                #pragma unroll
                for (int j = 0; j < 4; j++) {
                    float ic = 1.f / (M[j]+M[4+j]+M[8+j]+M[12+j]);
                    M[j]*=ic; M[4+j]*=ic; M[8+j]*=ic; M[12+j]*=ic;
                }
            }
            #pragma unroll
            for (int k = 0; k < 16; k++) g_Hres[slot*16+k] = M[k];
        }
        __syncthreads();

        float h0 = hpre[0], h1 = hpre[1], h2 = hpre[2], h3 = hpre[3];
        float hreg[8], hq = 0.f;
        #pragma unroll
        for (int u = 0; u < 8; u++) {
            float h = h0*st[0][u] + h1*st[1][u] + h2*st[2][u] + h3*st[3][u];
            hreg[u] = h; hq += h*h;
        }
        #pragma unroll
        for (int o = 16; o > 0; o >>= 1) hq += __shfl_down_sync(0xffffffffu, hq, o);
        if (lane == 0) red2[warp] = hq;
        __syncthreads();
        float sh = rsqrtf((red2[0]+red2[1]+red2[2]+red2[3]) / (float)DD + EPS_F);
        const float* snw = sw_norm_w + (size_t)e*DD;
        hf* hn = g_HN + ((size_t)e*CAP + row) * DD;
        #pragma unroll
        for (int u = 0; u < 8; u++) {
            int dd = tid + u*128;
            float v = hreg[u] * sh * snw[dd];
            hn[(dd & ~15) + posh(dd & 15)] = __float2half_rn(v);
        }
    }
}

// ---- combine res + post ----
__global__ void __launch_bounds__(128) k_out(const float* __restrict__ stream,
                                             float* __restrict__ outp)
{
    int token = blockIdx.x, b = token / TT, t = token % TT, tid = threadIdx.x;
    const float* sp0 = stream + ((size_t)b*NS*TT + t) * DD;
    float st[4][8], acc[4][8];
    #pragma unroll
    for (int i = 0; i < 4; i++)
        #pragma unroll
        for (int j = 0; j < 8; j++) {
            st[i][j] = sp0[(size_t)i*TT*DD + tid + j*128];
            acc[i][j] = 0.f;
        }
    for (int e = 0; e < EE; e++) {
        int row = g_row[token*EE + e];
        if (row < 0) continue;
        float g = g_gatev[token*EE + e];
        size_t slot = (size_t)e*CAP + row;
        float Hr[16], Hp[4];
        #pragma unroll
        for (int k = 0; k < 16; k++) Hr[k] = g_Hres[slot*16+k];
        #pragma unroll
        for (int i = 0; i < 4; i++) Hp[i] = g_Hpost[slot*4+i];
        const float* o = g_OUT + slot*DD;
        #pragma unroll
        for (int j = 0; j < 8; j++) {
            float ov = o[tid + j*128];
            #pragma unroll
            for (int i = 0; i < 4; i++) {
                float r = Hr[i*4]*st[0][j] + Hr[i*4+1]*st[1][j]
                        + Hr[i*4+2]*st[2][j] + Hr[i*4+3]*st[3][j];
                acc[i][j] += g * (r + Hp[i]*ov);
            }
        }
    }
    #pragma unroll
    for (int i = 0; i < 4; i++)
        #pragma unroll
        for (int j = 0; j < 8; j++)
            outp[((size_t)(b*NS+i)*TT + t)*DD + tid + j*128] = acc[i][j];
}

#define GSA(p, s) cudaGetSymbolAddress((void**)&p, s)

extern "C" void kernel_launch(void* const* d_in, const int* in_sizes, int n_in,
                              void* d_out, int out_size)
{
    (void)in_sizes; (void)n_in; (void)out_size;
    const float* stream   = (const float*)d_in[0];
    const float* router_w = (const float*)d_in[1];
    const float* mhc      = (const float*)d_in[2];
    const float* phi_pre  = (const float*)d_in[3];
    const float* phi_post = (const float*)d_in[4];
    const float* phi_res  = (const float*)d_in[5];
    const float* b_pre    = (const float*)d_in[6];
    const float* b_post   = (const float*)d_in[7];
    const float* b_res    = (const float*)d_in[8];
    const float* a_pre    = (const float*)d_in[9];
    const float* a_post   = (const float*)d_in[10];
    const float* a_res    = (const float*)d_in[11];
    const float* sw_nw    = (const float*)d_in[12];
    const float* wd_w     = (const float*)d_in[13];
    const float* wu_w     = (const float*)d_in[14];
    const float* gate_w   = (const float*)d_in[15];
    const float* up_w     = (const float*)d_in[16];
    const float* down_w   = (const float*)d_in[17];

    float* outp = (float*)d_out;
    float* out_gate = outp + (size_t)BB*NS*TT*DD;

    cudaFuncSetAttribute(k_gemm<0>, cudaFuncAttributeMaxDynamicSharedMemorySize, SMEM_DYN);
    cudaFuncSetAttribute(k_gemm<1>, cudaFuncAttributeMaxDynamicSharedMemorySize, SMEM_DYN);
    cudaFuncSetAttribute(k_gemm<2>, cudaFuncAttributeMaxDynamicSharedMemorySize, SMEM_DYN);
    cudaFuncSetAttribute(k_gemm<5>, cudaFuncAttributeMaxDynamicSharedMemorySize, SMEM_DYN);
    cudaFuncSetAttribute(k_gemmF, cudaFuncAttributeMaxDynamicSharedMemorySize, SMEM_F);

    hf *base, *HN, *T1, *P2, *phiW, *gt, *up, *dn;
    float *GS, *OUT, *dots;
    hf *wd, *wu;
    GSA(base, g_base); GSA(HN, g_HN); GSA(T1, g_T1); GSA(P2, g_P2);
    GSA(phiW, g_phiW); GSA(wd, g_wd); GSA(wu, g_wu); GSA(gt, g_gt);
    GSA(up, g_up); GSA(dn, g_dn);
    GSA(GS, g_GS); GSA(OUT, g_OUT); GSA(dots, g_dots);

    k_zero<<<1, 32>>>();
    k_gate<<<BT, 256>>>(stream, router_w, out_gate);
    k_pack<<<(EE*24*NDIM/16)/256, 256>>>(mhc, phi_pre, phi_post, phi_res);
    k_packall<<<4096, 256>>>(wd_w, wu_w, gate_w, up_w, down_w);

    // dots = base @ phiW^T  (N=384, K=4096)
    k_gemm<0><<<dim3(32,3,1), 256, SMEM_DYN>>>(base, NDIM, phiW, NDIM, 384, NDIM/KC,
                                               dots, (hf*)0, 384, (const float*)0, 0, BT);

    k_hn<<<BT, 128>>>(stream, b_pre, b_post, b_res, a_pre, a_post, a_res, sw_nw);

    dim3 gD(32, 8, EE);

    // T1 = silu(HN @ wd^T) -> interleaved half
    k_gemm<1><<<gD, 256, SMEM_DYN>>>(HN, DD, wd, DD, DD, DD/KC,
                                     (float*)0, T1, DD, (const float*)0, 0, -1);
    // GS = sigmoid(T1 @ wu^T) -> f32
    k_gemm<2><<<gD, 256, SMEM_DYN>>>(T1, DD, wu, DD, DD, DD/KC,
                                     GS, (hf*)0, DD, (const float*)0, 0, -1);
    // P2 = silu(HN @ gt^T) * (HN @ up^T) -> interleaved half (pad to LDP)
    k_gemmF<<<dim3(32,13,EE), 512, SMEM_F>>>(HN, gt, up, P2);
    // OUT = (P2 @ dn^T) * GS -> f32
    k_gemm<5><<<gD, 256, SMEM_DYN>>>(P2, LDP, dn, LDP, DD, LDP/KC,
                                     OUT, (hf*)0, DD, GS, DD, -1);

    k_out<<<BT, 128>>>(stream, outp);
}